// round 6
// baseline (speedup 1.0000x reference)
#include <cuda_runtime.h>
#include <math.h>

// ---------------------------------------------------------------------------
// TemporalCausalAttention  B=4 N=256 T=64 D=128 DR=32 DH=128
//
// Restructured pipeline (all fp32):
//  prep : pack Wp = [Wq*rs | Wk | W1(bias bf) | W2 | (Wq^T Wr)*rs], wqb = Wq^T br
//  ej   : Ej[b,j,e] = (sum_t dH[b,j,t,:]) @ W4^T
//  qb   : qb[b,i,t] = rs*(H.wqb + bq.br)
//  P1   : fused GEMM H(65536x128) @ Wp^T(128x544) -> qT,kT,A'(+bf),Btil(+Ej),qr
//  P2   : S[b,i,t,j]  = qr[b,i,t,:].R[b,i,j,:] + qb          (scores, r-term)
//  P3   : S[b,i,t,j] += q[b,i,t,:].k[b,j,t,:]                (per-(b,t) GEMM)
//  P4a  : softmax over t per (b,i,j), mask j==i, wsum; w written back to S
//  P4b  : WR=w.R (per b,i);  P = A'*wsum + WR@W3^T
//  P5   : P[b,i,t,:] += sum_j w[b,i,j,t]*Btil[b,j,t,:]       (per-(b,t) GEMM)
//  P6   : out = LayerNorm(H + P)*gamma + beta
// ---------------------------------------------------------------------------

#define BB   4
#define NN   256
#define TT   64
#define DD   128
#define DRR  32
#define NCOL 544
#define RSX  0.08838834764831844f   // 1/sqrt(128)

__device__ __align__(16) float g_Wp[NCOL * 128];
__device__ float g_bp[NCOL];
__device__ float g_wqb[128];
__device__ float g_bqb;
__device__ __align__(16) float g_Ej[BB * NN * DD];
__device__ float g_qb[BB * NN * TT];
__device__ __align__(16) float g_qT[BB * TT * NN * DD];   // (b,t,n,h)
__device__ __align__(16) float g_kT[BB * TT * NN * DD];   // (b,t,n,h)
__device__ __align__(16) float g_Ap[BB * NN * TT * DD];   // (b,n,t,e)  A+bf
__device__ __align__(16) float g_Bt[BB * TT * NN * DD];   // (b,t,n,e)  H@W2+Ej
__device__ __align__(16) float g_qr[BB * NN * TT * DRR];  // (b,n,t,r)
__device__ __align__(16) float g_S [BB * NN * TT * NN];   // (b,i,t,j) scores->w
__device__ __align__(16) float g_P [BB * NN * TT * DD];   // (b,n,t,e)
__device__ float g_wsum[BB * NN * TT];

// --------------------------------------------------------------- weight prep
__global__ void k_prep(const float* __restrict__ Wq, const float* __restrict__ bq,
                       const float* __restrict__ Wk, const float* __restrict__ bk,
                       const float* __restrict__ Wr, const float* __restrict__ br,
                       const float* __restrict__ Wf, const float* __restrict__ bf) {
    const int c = blockIdx.x, d = threadIdx.x;
    if (c < NCOL) {
        float w = 0.f, bias = 0.f;
        if (c < 128)       { w = Wq[c*128 + d] * RSX;           bias = bq[c] * RSX; }
        else if (c < 256)  { int h = c-128; w = Wk[h*128 + d];  bias = bk[h]; }
        else if (c < 384)  { int e = c-256; w = Wf[e*416 + d];  bias = bf[e]; }
        else if (c < 512)  { int e = c-384; w = Wf[e*416 + 128 + d]; bias = 0.f; }
        else {
            int r = c - 512;
            float a = 0.f, bbv = 0.f;
            for (int h = 0; h < 128; h++) {
                a   += Wq[h*128 + d] * Wr[h*32 + r];
                bbv += bq[h]         * Wr[h*32 + r];
            }
            w = a * RSX; bias = bbv * RSX;
        }
        g_Wp[c*128 + d] = w;
        if (d == 0) g_bp[c] = bias;
    } else {   // c == 544: wqb[d] = sum_h Wq[h,d]*br[h],  bqb = bq.br
        float a = 0.f;
        for (int h = 0; h < 128; h++) a += Wq[h*128 + d] * br[h];
        g_wqb[d] = a;
        if (d == 0) {
            float bbv = 0.f;
            for (int h = 0; h < 128; h++) bbv += bq[h] * br[h];
            g_bqb = bbv;
        }
    }
}

// ------------------------------------------------------------------------ Ej
__global__ void k_ej(const float* __restrict__ dH, const float* __restrict__ Wf) {
    const int bn = blockIdx.x;        // b*256+n
    const int d  = threadIdx.x;       // 128
    __shared__ float ds[128];
    float s = 0.f;
    const float* p = dH + (size_t)bn * TT * DD + d;
    #pragma unroll 8
    for (int t = 0; t < TT; t++) s += p[t * DD];
    ds[d] = s;
    __syncthreads();
    float acc = 0.f;
    const float* w4 = Wf + (size_t)d * 416 + 288;   // W4 row e=d
    #pragma unroll 8
    for (int dd = 0; dd < 128; dd++) acc += ds[dd] * w4[dd];
    g_Ej[(size_t)bn * 128 + d] = acc;
}

// ------------------------------------------------------------------------ qb
__global__ __launch_bounds__(128) void k_qb(const float* __restrict__ Hm) {
    const int row = blockIdx.x;       // (b*256+i)*64+t
    const int d   = threadIdx.x;
    float v = Hm[(size_t)row * 128 + d] * g_wqb[d];
    #pragma unroll
    for (int o = 16; o > 0; o >>= 1) v += __shfl_xor_sync(0xffffffffu, v, o);
    __shared__ float sm[4];
    if ((d & 31) == 0) sm[d >> 5] = v;
    __syncthreads();
    if (d == 0) g_qb[row] = RSX * (sm[0] + sm[1] + sm[2] + sm[3] + g_bqb);
}

// --------------------------------------------- P1: fused projection GEMM (NT)
__global__ __launch_bounds__(256) void k_p1(const float* __restrict__ Hm) {
    __shared__ float As[128][20];
    __shared__ float Bs[16][132];
    __shared__ float bias_s[128];
    const int tid = threadIdx.x;
    const int r0 = blockIdx.x * 128;
    const int c0 = blockIdx.y * 128;
    const int tx = tid & 15, ty = tid >> 4;
    if (tid < 128) { int c = c0 + tid; bias_s[tid] = (c < NCOL) ? g_bp[c] : 0.f; }
    float acc[8][8];
    #pragma unroll
    for (int i = 0; i < 8; i++)
        #pragma unroll
        for (int j = 0; j < 8; j++) acc[i][j] = 0.f;
    const int lr = tid >> 2;
    const int lk = (tid & 3) * 4;
    for (int k0 = 0; k0 < 128; k0 += 16) {
        #pragma unroll
        for (int it = 0; it < 2; it++) {
            int row = lr + it * 64;
            float4 av = *(const float4*)(Hm + (size_t)(r0 + row) * 128 + k0 + lk);
            *(float4*)&As[row][lk] = av;
            int col = c0 + row;
            float4 bv = make_float4(0.f, 0.f, 0.f, 0.f);
            if (col < NCOL) bv = *(const float4*)(g_Wp + (size_t)col * 128 + k0 + lk);
            Bs[lk + 0][row] = bv.x; Bs[lk + 1][row] = bv.y;
            Bs[lk + 2][row] = bv.z; Bs[lk + 3][row] = bv.w;
        }
        __syncthreads();
        #pragma unroll
        for (int kk = 0; kk < 16; kk++) {
            float a[8], b[8];
            #pragma unroll
            for (int i = 0; i < 8; i++) a[i] = As[ty * 8 + i][kk];
            float4 b0 = *(float4*)&Bs[kk][tx * 4];
            float4 b1 = *(float4*)&Bs[kk][64 + tx * 4];
            b[0] = b0.x; b[1] = b0.y; b[2] = b0.z; b[3] = b0.w;
            b[4] = b1.x; b[5] = b1.y; b[6] = b1.z; b[7] = b1.w;
            #pragma unroll
            for (int i = 0; i < 8; i++)
                #pragma unroll
                for (int j = 0; j < 8; j++) acc[i][j] += a[i] * b[j];
        }
        __syncthreads();
    }
    #pragma unroll
    for (int i = 0; i < 8; i++) {
        int r = r0 + ty * 8 + i;
        int b = r >> 14, n = (r >> 6) & 255, t = r & 63;
        size_t tb = ((size_t)((b * TT + t) * NN + n)) * 128;
        #pragma unroll
        for (int g = 0; g < 2; g++) {
            int c = c0 + g * 64 + tx * 4;
            if (c >= NCOL) continue;
            int bs = g * 64 + tx * 4;
            float v0 = acc[i][g*4+0] + bias_s[bs+0];
            float v1 = acc[i][g*4+1] + bias_s[bs+1];
            float v2 = acc[i][g*4+2] + bias_s[bs+2];
            float v3 = acc[i][g*4+3] + bias_s[bs+3];
            if (c < 128) {
                *(float4*)(g_qT + tb + c) = make_float4(v0, v1, v2, v3);
            } else if (c < 256) {
                *(float4*)(g_kT + tb + (c - 128)) = make_float4(v0, v1, v2, v3);
            } else if (c < 384) {
                *(float4*)(g_Ap + (size_t)r * 128 + (c - 256)) = make_float4(v0, v1, v2, v3);
            } else if (c < 512) {
                const float* ej = g_Ej + (size_t)(b * NN + n) * 128 + (c - 384);
                *(float4*)(g_Bt + tb + (c - 384)) =
                    make_float4(v0 + ej[0], v1 + ej[1], v2 + ej[2], v3 + ej[3]);
            } else {
                *(float4*)(g_qr + (size_t)r * 32 + (c - 512)) = make_float4(v0, v1, v2, v3);
            }
        }
    }
}

// --------------------------------------------- P2: S init = qr.R + qb
__global__ __launch_bounds__(256) void k_p2(const float* __restrict__ R) {
    __shared__ float qrs[64][36];
    __shared__ float Rst[32][265];
    const int bi = blockIdx.x;
    const int tid = threadIdx.x;
    #pragma unroll
    for (int it = 0; it < 2; it++) {
        int id = tid + it * 256;
        int t = id >> 3, rq = (id & 7) * 4;
        float4 v = *(const float4*)(g_qr + (size_t)bi * (TT * DRR) + t * DRR + rq);
        *(float4*)&qrs[t][rq] = v;
    }
    // R tile: 256 rows x 32 cols = 2048 float4 loads -> 8 iterations
    #pragma unroll
    for (int it = 0; it < 8; it++) {
        int id = tid + it * 256;                 // 0..2047
        int j = id >> 3, rq = (id & 7) * 4;      // j 0..255, rq {0,4,...,28}
        float4 v = *(const float4*)(R + (size_t)bi * (NN * DRR) + (size_t)j * DRR + rq);
        Rst[rq + 0][j] = v.x; Rst[rq + 1][j] = v.y;
        Rst[rq + 2][j] = v.z; Rst[rq + 3][j] = v.w;
    }
    __syncthreads();
    const int jl = tid & 31, tg = tid >> 5;
    float acc[8][8];
    #pragma unroll
    for (int a = 0; a < 8; a++)
        #pragma unroll
        for (int b = 0; b < 8; b++) acc[a][b] = 0.f;
    #pragma unroll
    for (int r = 0; r < 32; r++) {
        float qv[8], rv[8];
        #pragma unroll
        for (int tk = 0; tk < 8; tk++) qv[tk] = qrs[tg + 8 * tk][r];
        #pragma unroll
        for (int jc = 0; jc < 8; jc++) rv[jc] = Rst[r][jl + 32 * jc];
        #pragma unroll
        for (int tk = 0; tk < 8; tk++)
            #pragma unroll
            for (int jc = 0; jc < 8; jc++) acc[tk][jc] += qv[tk] * rv[jc];
    }
    #pragma unroll
    for (int tk = 0; tk < 8; tk++) {
        int t = tg + 8 * tk;
        float qb = g_qb[bi * TT + t];
        size_t base = ((size_t)bi * TT + t) * NN;
        #pragma unroll
        for (int jc = 0; jc < 8; jc++)
            g_S[base + jl + 32 * jc] = acc[tk][jc] + qb;
    }
}

// --------------------------------------------- P3: S += q.k^T  (per (b,t), NT)
__global__ __launch_bounds__(256) void k_p3() {
    __shared__ float As[128][20];
    __shared__ float Bs[16][132];
    const int tid = threadIdx.x;
    const int bt = blockIdx.y;
    const int i0 = (blockIdx.x & 1) * 128;
    const int j0 = (blockIdx.x >> 1) * 128;
    const float* Aa = g_qT + (size_t)bt * (NN * 128) + (size_t)i0 * 128;
    const float* Bb = g_kT + (size_t)bt * (NN * 128) + (size_t)j0 * 128;
    const int tx = tid & 15, ty = tid >> 4;
    float acc[8][8];
    #pragma unroll
    for (int i = 0; i < 8; i++)
        #pragma unroll
        for (int j = 0; j < 8; j++) acc[i][j] = 0.f;
    const int lr = tid >> 2;
    const int lk = (tid & 3) * 4;
    for (int k0 = 0; k0 < 128; k0 += 16) {
        #pragma unroll
        for (int it = 0; it < 2; it++) {
            int row = lr + it * 64;
            float4 av = *(const float4*)(Aa + (size_t)row * 128 + k0 + lk);
            *(float4*)&As[row][lk] = av;
            float4 bv = *(const float4*)(Bb + (size_t)row * 128 + k0 + lk);
            Bs[lk + 0][row] = bv.x; Bs[lk + 1][row] = bv.y;
            Bs[lk + 2][row] = bv.z; Bs[lk + 3][row] = bv.w;
        }
        __syncthreads();
        #pragma unroll
        for (int kk = 0; kk < 16; kk++) {
            float a[8], b[8];
            #pragma unroll
            for (int i = 0; i < 8; i++) a[i] = As[ty * 8 + i][kk];
            float4 b0 = *(float4*)&Bs[kk][tx * 4];
            float4 b1 = *(float4*)&Bs[kk][64 + tx * 4];
            b[0] = b0.x; b[1] = b0.y; b[2] = b0.z; b[3] = b0.w;
            b[4] = b1.x; b[5] = b1.y; b[6] = b1.z; b[7] = b1.w;
            #pragma unroll
            for (int i = 0; i < 8; i++)
                #pragma unroll
                for (int j = 0; j < 8; j++) acc[i][j] += a[i] * b[j];
        }
        __syncthreads();
    }
    const int b = bt >> 6, t = bt & 63;
    #pragma unroll
    for (int i = 0; i < 8; i++) {
        int irow = i0 + ty * 8 + i;
        size_t base = ((size_t)((b * NN + irow) * TT + t)) * NN + j0;
        #pragma unroll
        for (int g = 0; g < 2; g++) {
            int cc = g * 64 + tx * 4;
            float4 o = *(float4*)(g_S + base + cc);
            o.x += acc[i][g*4+0]; o.y += acc[i][g*4+1];
            o.z += acc[i][g*4+2]; o.w += acc[i][g*4+3];
            *(float4*)(g_S + base + cc) = o;
        }
    }
}

// --------------------------------------------- P4a: softmax over t, mask, wsum
__global__ __launch_bounds__(256) void k_p4a() {
    const int bi = blockIdx.x;
    const int i = bi & 255;
    const int j = threadIdx.x;
    size_t base = (size_t)bi * (TT * NN) + j;
    float v[64];
    float mx = -1e30f;
    #pragma unroll
    for (int t = 0; t < 64; t++) { v[t] = g_S[base + t * NN]; mx = fmaxf(mx, v[t]); }
    float s = 0.f;
    #pragma unroll
    for (int t = 0; t < 64; t++) { v[t] = __expf(v[t] - mx); s += v[t]; }
    float inv = (j == i) ? 0.f : (1.f / s);
    #pragma unroll
    for (int t = 0; t < 64; t++) { v[t] *= inv; g_S[base + t * NN] = v[t]; }
    __shared__ float ws[8][64];
    const int lane = j & 31, wp = j >> 5;
    #pragma unroll
    for (int t = 0; t < 64; t++) {
        float r = v[t];
        r += __shfl_xor_sync(0xffffffffu, r, 16);
        r += __shfl_xor_sync(0xffffffffu, r, 8);
        r += __shfl_xor_sync(0xffffffffu, r, 4);
        r += __shfl_xor_sync(0xffffffffu, r, 2);
        r += __shfl_xor_sync(0xffffffffu, r, 1);
        if (lane == 0) ws[wp][t] = r;
    }
    __syncthreads();
    if (j < 64) {
        float s2 = 0.f;
        #pragma unroll
        for (int w = 0; w < 8; w++) s2 += ws[w][j];
        g_wsum[bi * TT + j] = s2;
    }
}

// ------------------------------- P4b: WR = w.R ; P = A'*wsum + WR@W3^T
__global__ __launch_bounds__(256) void k_p4b(const float* __restrict__ R,
                                             const float* __restrict__ Wf) {
    __shared__ float wj[64][72];
    __shared__ float Rs[64][36];
    __shared__ float WRs[64][32];
    __shared__ float wsum_s[64];
    const int bi = blockIdx.x;
    const int tid = threadIdx.x;
    const int rq = tid & 7, tq = tid >> 3;     // tq 0..31; t in {tq, tq+32}
    float a00 = 0.f, a01 = 0.f, a02 = 0.f, a03 = 0.f;
    float a10 = 0.f, a11 = 0.f, a12 = 0.f, a13 = 0.f;
    for (int jc = 0; jc < 4; jc++) {
        const int j0 = jc * 64;
        #pragma unroll
        for (int it = 0; it < 4; it++) {
            int id = tid + it * 256;
            int t = id >> 4, j4 = (id & 15) * 4;
            float4 v = *(const float4*)(g_S + (size_t)bi * (TT * NN) + (size_t)t * NN + j0 + j4);
            *(float4*)&wj[t][j4] = v;
        }
        #pragma unroll
        for (int it = 0; it < 2; it++) {
            int id = tid + it * 256;
            int jj = id >> 3, rr4 = (id & 7) * 4;
            float4 v = *(const float4*)(R + ((size_t)bi * NN + j0 + jj) * DRR + rr4);
            *(float4*)&Rs[jj][rr4] = v;
        }
        __syncthreads();
        #pragma unroll 8
        for (int jj = 0; jj < 64; jj++) {
            float4 rv = *(float4*)&Rs[jj][rq * 4];
            float w0 = wj[tq][jj];
            float w1 = wj[tq + 32][jj];
            a00 += w0 * rv.x; a01 += w0 * rv.y; a02 += w0 * rv.z; a03 += w0 * rv.w;
            a10 += w1 * rv.x; a11 += w1 * rv.y; a12 += w1 * rv.z; a13 += w1 * rv.w;
        }
        __syncthreads();
    }
    *(float4*)&WRs[tq][rq * 4]      = make_float4(a00, a01, a02, a03);
    *(float4*)&WRs[tq + 32][rq * 4] = make_float4(a10, a11, a12, a13);
    if (tid < 64) wsum_s[tid] = g_wsum[bi * TT + tid];
    __syncthreads();
    // phase 2: P[t][e] = Ap[t][e]*wsum[t] + sum_r WRs[t][r]*W3[e][r]
    const int e = tid & 127, th = tid >> 7;
    float w3r[32];
    #pragma unroll
    for (int q = 0; q < 8; q++) {
        float4 v = *(const float4*)(Wf + (size_t)e * 416 + 256 + q * 4);
        w3r[q*4+0] = v.x; w3r[q*4+1] = v.y; w3r[q*4+2] = v.z; w3r[q*4+3] = v.w;
    }
    #pragma unroll 4
    for (int tt = 0; tt < 32; tt++) {
        int t = th * 32 + tt;
        size_t idx = ((size_t)bi * TT + t) * 128 + e;
        float acc = g_Ap[idx] * wsum_s[t];
        #pragma unroll
        for (int q = 0; q < 8; q++) {
            float4 wr = *(float4*)&WRs[t][q * 4];
            acc += wr.x * w3r[q*4+0] + wr.y * w3r[q*4+1]
                 + wr.z * w3r[q*4+2] + wr.w * w3r[q*4+3];
        }
        g_P[idx] = acc;
    }
}

// --------------------------------------------- P5: P += w @ Btil (per (b,t), NN)
__global__ __launch_bounds__(256) void k_p5() {
    __shared__ float As[128][20];
    __shared__ float Bs[16][128];
    const int tid = threadIdx.x;
    const int bt = blockIdx.y;
    const int i0 = blockIdx.x * 128;
    const int b = bt >> 6, t = bt & 63;
    const int tx = tid & 15, ty = tid >> 4;
    float acc[8][8];
    #pragma unroll
    for (int i = 0; i < 8; i++)
        #pragma unroll
        for (int j = 0; j < 8; j++) acc[i][j] = 0.f;
    const int lr = tid >> 2;
    const int lk = (tid & 3) * 4;
    for (int k0 = 0; k0 < 256; k0 += 16) {
        #pragma unroll
        for (int it = 0; it < 2; it++) {
            int row = lr + it * 64;
            size_t abase = ((size_t)((b * NN + i0 + row) * TT + t)) * NN;
            float4 av = *(const float4*)(g_S + abase + k0 + lk);
            *(float4*)&As[row][lk] = av;
        }
        #pragma unroll
        for (int it = 0; it < 2; it++) {
            int id = tid + it * 256;
            int kk = id >> 5, e4 = (id & 31) * 4;
            float4 bv = *(const float4*)(g_Bt + (size_t)bt * (NN * 128) + (size_t)(k0 + kk) * 128 + e4);
            *(float4*)&Bs[kk][e4] = bv;
        }
        __syncthreads();
        #pragma unroll
        for (int kk = 0; kk < 16; kk++) {
            float a[8], bfr[8];
            #pragma unroll
            for (int i = 0; i < 8; i++) a[i] = As[ty * 8 + i][kk];
            float4 b0 = *(float4*)&Bs[kk][tx * 4];
            float4 b1 = *(float4*)&Bs[kk][64 + tx * 4];
            bfr[0] = b0.x; bfr[1] = b0.y; bfr[2] = b0.z; bfr[3] = b0.w;
            bfr[4] = b1.x; bfr[5] = b1.y; bfr[6] = b1.z; bfr[7] = b1.w;
            #pragma unroll
            for (int i = 0; i < 8; i++)
                #pragma unroll
                for (int j = 0; j < 8; j++) acc[i][j] += a[i] * bfr[j];
        }
        __syncthreads();
    }
    #pragma unroll
    for (int i = 0; i < 8; i++) {
        int irow = i0 + ty * 8 + i;
        size_t base = ((size_t)((b * NN + irow) * TT + t)) * 128;
        #pragma unroll
        for (int g = 0; g < 2; g++) {
            int cc = g * 64 + tx * 4;
            float4 o = *(float4*)(g_P + base + cc);
            o.x += acc[i][g*4+0]; o.y += acc[i][g*4+1];
            o.z += acc[i][g*4+2]; o.w += acc[i][g*4+3];
            *(float4*)(g_P + base + cc) = o;
        }
    }
}

// --------------------------------------------- P6: layernorm
__global__ __launch_bounds__(128) void k_p6(const float* __restrict__ Hm,
                                            const float* __restrict__ gamma,
                                            const float* __restrict__ beta,
                                            float* __restrict__ out) {
    const int row = blockIdx.x;
    const int d = threadIdx.x;
    size_t idx = (size_t)row * 128 + d;
    float x = Hm[idx] + g_P[idx];
    __shared__ float sm[4], sm2[4];
    float v = x;
    #pragma unroll
    for (int o = 16; o > 0; o >>= 1) v += __shfl_xor_sync(0xffffffffu, v, o);
    if ((d & 31) == 0) sm[d >> 5] = v;
    __syncthreads();
    float mu = (sm[0] + sm[1] + sm[2] + sm[3]) * (1.f / 128.f);
    float dx = x - mu;
    v = dx * dx;
    #pragma unroll
    for (int o = 16; o > 0; o >>= 1) v += __shfl_xor_sync(0xffffffffu, v, o);
    if ((d & 31) == 0) sm2[d >> 5] = v;
    __syncthreads();
    float var = (sm2[0] + sm2[1] + sm2[2] + sm2[3]) * (1.f / 128.f);
    out[idx] = dx * rsqrtf(var + 1e-5f) * gamma[d] + beta[d];
}

// ---------------------------------------------------------------------------
extern "C" void kernel_launch(void* const* d_in, const int* in_sizes, int n_in,
                              void* d_out, int out_size) {
    const float* H     = (const float*)d_in[0];
    const float* R     = (const float*)d_in[1];
    const float* dH    = (const float*)d_in[2];
    const float* Wq    = (const float*)d_in[3];
    const float* bq    = (const float*)d_in[4];
    const float* Wk    = (const float*)d_in[5];
    const float* bk    = (const float*)d_in[6];
    const float* Wr    = (const float*)d_in[7];
    const float* br    = (const float*)d_in[8];
    const float* Wf    = (const float*)d_in[9];
    const float* bf    = (const float*)d_in[10];
    const float* gamma = (const float*)d_in[11];
    const float* beta  = (const float*)d_in[12];
    float* out = (float*)d_out;

    k_prep<<<NCOL + 1, 128>>>(Wq, bq, Wk, bk, Wr, br, Wf, bf);
    k_ej<<<BB * NN, 128>>>(dH, Wf);
    k_qb<<<BB * NN * TT, 128>>>(H);
    k_p1<<<dim3(512, 5), 256>>>(H);
    k_p2<<<BB * NN, 256>>>(R);
    k_p3<<<dim3(4, BB * TT), 256>>>();
    k_p4a<<<BB * NN, 256>>>();
    k_p4b<<<BB * NN, 256>>>(R, Wf);
    k_p5<<<dim3(2, BB * TT), 256>>>();
    k_p6<<<BB * NN * TT, 128>>>(H, gamma, beta, out);
}

// round 8
// speedup vs baseline: 1.1263x; 1.1263x over previous
#include <cuda_runtime.h>
#include <math.h>

// ---------------------------------------------------------------------------
// TemporalCausalAttention  B=4 N=256 T=64 D=128 DR=32 DH=128
// R7: f32x2 packed FMA in the three GEMM inner loops + 2 CTAs/SM.
// ---------------------------------------------------------------------------

#define BB   4
#define NN   256
#define TT   64
#define DD   128
#define DRR  32
#define NCOL 544
#define RSX  0.08838834764831844f   // 1/sqrt(128)

typedef unsigned long long ull;
__device__ __forceinline__ void fma2(ull &c, ull a, ull b) {
    asm("fma.rn.f32x2 %0, %1, %2, %0;" : "+l"(c) : "l"(a), "l"(b));
}
__device__ __forceinline__ ull dup2(float x) {
    ull r; asm("mov.b64 %0, {%1, %1};" : "=l"(r) : "f"(x)); return r;
}
__device__ __forceinline__ float2 unpk(ull v) {
    float2 f; asm("mov.b64 {%0, %1}, %2;" : "=f"(f.x), "=f"(f.y) : "l"(v)); return f;
}

__device__ __align__(16) float g_Wp[NCOL * 128];
__device__ float g_bp[NCOL];
__device__ float g_wqb[128];
__device__ float g_bqb;
__device__ __align__(16) float g_Ej[BB * NN * DD];
__device__ float g_qb[BB * NN * TT];
__device__ __align__(16) float g_qT[BB * TT * NN * DD];   // (b,t,n,h)
__device__ __align__(16) float g_kT[BB * TT * NN * DD];   // (b,t,n,h)
__device__ __align__(16) float g_Ap[BB * NN * TT * DD];   // (b,n,t,e)  A+bf
__device__ __align__(16) float g_Bt[BB * TT * NN * DD];   // (b,t,n,e)  H@W2+Ej
__device__ __align__(16) float g_qr[BB * NN * TT * DRR];  // (b,n,t,r)
__device__ __align__(16) float g_S [BB * NN * TT * NN];   // (b,i,t,j) scores->w
__device__ __align__(16) float g_P [BB * NN * TT * DD];   // (b,n,t,e)
__device__ float g_wsum[BB * NN * TT];

// --------------------------------------------------------------- weight prep
__global__ void k_prep(const float* __restrict__ Wq, const float* __restrict__ bq,
                       const float* __restrict__ Wk, const float* __restrict__ bk,
                       const float* __restrict__ Wr, const float* __restrict__ br,
                       const float* __restrict__ Wf, const float* __restrict__ bf) {
    const int c = blockIdx.x, d = threadIdx.x;
    if (c < NCOL) {
        float w = 0.f, bias = 0.f;
        if (c < 128)       { w = Wq[c*128 + d] * RSX;           bias = bq[c] * RSX; }
        else if (c < 256)  { int h = c-128; w = Wk[h*128 + d];  bias = bk[h]; }
        else if (c < 384)  { int e = c-256; w = Wf[e*416 + d];  bias = bf[e]; }
        else if (c < 512)  { int e = c-384; w = Wf[e*416 + 128 + d]; bias = 0.f; }
        else {
            int r = c - 512;
            float a = 0.f, bbv = 0.f;
            for (int h = 0; h < 128; h++) {
                a   += Wq[h*128 + d] * Wr[h*32 + r];
                bbv += bq[h]         * Wr[h*32 + r];
            }
            w = a * RSX; bias = bbv * RSX;
        }
        g_Wp[c*128 + d] = w;
        if (d == 0) g_bp[c] = bias;
    } else {   // c == 544: wqb[d] = sum_h Wq[h,d]*br[h],  bqb = bq.br
        float a = 0.f;
        for (int h = 0; h < 128; h++) a += Wq[h*128 + d] * br[h];
        g_wqb[d] = a;
        if (d == 0) {
            float bbv = 0.f;
            for (int h = 0; h < 128; h++) bbv += bq[h] * br[h];
            g_bqb = bbv;
        }
    }
}

// ------------------------------------------------------------------------ Ej
__global__ void k_ej(const float* __restrict__ dH, const float* __restrict__ Wf) {
    const int bn = blockIdx.x;        // b*256+n
    const int d  = threadIdx.x;       // 128
    __shared__ float ds[128];
    float s = 0.f;
    const float* p = dH + (size_t)bn * TT * DD + d;
    #pragma unroll 8
    for (int t = 0; t < TT; t++) s += p[t * DD];
    ds[d] = s;
    __syncthreads();
    float acc = 0.f;
    const float* w4 = Wf + (size_t)d * 416 + 288;   // W4 row e=d
    #pragma unroll 8
    for (int dd = 0; dd < 128; dd++) acc += ds[dd] * w4[dd];
    g_Ej[(size_t)bn * 128 + d] = acc;
}

// ------------------------------------------------------------------------ qb
__global__ __launch_bounds__(128) void k_qb(const float* __restrict__ Hm) {
    const int row = blockIdx.x;       // (b*256+i)*64+t
    const int d   = threadIdx.x;
    float v = Hm[(size_t)row * 128 + d] * g_wqb[d];
    #pragma unroll
    for (int o = 16; o > 0; o >>= 1) v += __shfl_xor_sync(0xffffffffu, v, o);
    __shared__ float sm[4];
    if ((d & 31) == 0) sm[d >> 5] = v;
    __syncthreads();
    if (d == 0) g_qb[row] = RSX * (sm[0] + sm[1] + sm[2] + sm[3] + g_bqb);
}

// --------------------------------------------- P1: fused projection GEMM (NT)
__global__ __launch_bounds__(256, 2) void k_p1(const float* __restrict__ Hm) {
    __shared__ float As[128][20];
    __shared__ float Bs[16][132];
    __shared__ float bias_s[128];
    const int tid = threadIdx.x;
    const int r0 = blockIdx.x * 128;
    const int c0 = blockIdx.y * 128;
    const int tx = tid & 15, ty = tid >> 4;
    if (tid < 128) { int c = c0 + tid; bias_s[tid] = (c < NCOL) ? g_bp[c] : 0.f; }
    ull acc2[8][4];
    #pragma unroll
    for (int i = 0; i < 8; i++)
        #pragma unroll
        for (int p = 0; p < 4; p++) acc2[i][p] = 0ull;
    const int lr = tid >> 2;
    const int lk = (tid & 3) * 4;
    for (int k0 = 0; k0 < 128; k0 += 16) {
        #pragma unroll
        for (int it = 0; it < 2; it++) {
            int row = lr + it * 64;
            float4 av = *(const float4*)(Hm + (size_t)(r0 + row) * 128 + k0 + lk);
            *(float4*)&As[row][lk] = av;
            int col = c0 + row;
            float4 bv = make_float4(0.f, 0.f, 0.f, 0.f);
            if (col < NCOL) bv = *(const float4*)(g_Wp + (size_t)col * 128 + k0 + lk);
            Bs[lk + 0][row] = bv.x; Bs[lk + 1][row] = bv.y;
            Bs[lk + 2][row] = bv.z; Bs[lk + 3][row] = bv.w;
        }
        __syncthreads();
        #pragma unroll
        for (int kk = 0; kk < 16; kk++) {
            const float* brow = &Bs[kk][0];
            float4 b0 = *(const float4*)(brow + tx * 4);
            float4 b1 = *(const float4*)(brow + 64 + tx * 4);
            ull b2[4];
            b2[0] = ((ull*)&b0)[0]; b2[1] = ((ull*)&b0)[1];
            b2[2] = ((ull*)&b1)[0]; b2[3] = ((ull*)&b1)[1];
            #pragma unroll
            for (int i = 0; i < 8; i++) {
                ull a2 = dup2(As[ty * 8 + i][kk]);
                fma2(acc2[i][0], a2, b2[0]);
                fma2(acc2[i][1], a2, b2[1]);
                fma2(acc2[i][2], a2, b2[2]);
                fma2(acc2[i][3], a2, b2[3]);
            }
        }
        __syncthreads();
    }
    #pragma unroll
    for (int i = 0; i < 8; i++) {
        int r = r0 + ty * 8 + i;
        int b = r >> 14, n = (r >> 6) & 255, t = r & 63;
        size_t tb = ((size_t)((b * TT + t) * NN + n)) * 128;
        float v[8];
        #pragma unroll
        for (int p = 0; p < 4; p++) {
            float2 f = unpk(acc2[i][p]);
            v[p * 2] = f.x; v[p * 2 + 1] = f.y;
        }
        #pragma unroll
        for (int g = 0; g < 2; g++) {
            int c = c0 + g * 64 + tx * 4;
            if (c >= NCOL) continue;
            int bs = g * 64 + tx * 4;
            float v0 = v[g*4+0] + bias_s[bs+0];
            float v1 = v[g*4+1] + bias_s[bs+1];
            float v2 = v[g*4+2] + bias_s[bs+2];
            float v3 = v[g*4+3] + bias_s[bs+3];
            if (c < 128) {
                *(float4*)(g_qT + tb + c) = make_float4(v0, v1, v2, v3);
            } else if (c < 256) {
                *(float4*)(g_kT + tb + (c - 128)) = make_float4(v0, v1, v2, v3);
            } else if (c < 384) {
                *(float4*)(g_Ap + (size_t)r * 128 + (c - 256)) = make_float4(v0, v1, v2, v3);
            } else if (c < 512) {
                const float* ej = g_Ej + (size_t)(b * NN + n) * 128 + (c - 384);
                *(float4*)(g_Bt + tb + (c - 384)) =
                    make_float4(v0 + ej[0], v1 + ej[1], v2 + ej[2], v3 + ej[3]);
            } else {
                *(float4*)(g_qr + (size_t)r * 32 + (c - 512)) = make_float4(v0, v1, v2, v3);
            }
        }
    }
}

// --------------------------------------------- P2: S init = qr.R + qb
__global__ __launch_bounds__(256) void k_p2(const float* __restrict__ R) {
    __shared__ float qrs[64][36];
    __shared__ float Rst[32][265];
    const int bi = blockIdx.x;
    const int tid = threadIdx.x;
    #pragma unroll
    for (int it = 0; it < 2; it++) {
        int id = tid + it * 256;
        int t = id >> 3, rq = (id & 7) * 4;
        float4 v = *(const float4*)(g_qr + (size_t)bi * (TT * DRR) + t * DRR + rq);
        *(float4*)&qrs[t][rq] = v;
    }
    // R tile: 256 rows x 32 cols = 2048 float4 loads -> 8 iterations
    #pragma unroll
    for (int it = 0; it < 8; it++) {
        int id = tid + it * 256;                 // 0..2047
        int j = id >> 3, rq = (id & 7) * 4;      // j 0..255, rq {0,4,...,28}
        float4 v = *(const float4*)(R + (size_t)bi * (NN * DRR) + (size_t)j * DRR + rq);
        Rst[rq + 0][j] = v.x; Rst[rq + 1][j] = v.y;
        Rst[rq + 2][j] = v.z; Rst[rq + 3][j] = v.w;
    }
    __syncthreads();
    const int jl = tid & 31, tg = tid >> 5;
    float acc[8][8];
    #pragma unroll
    for (int a = 0; a < 8; a++)
        #pragma unroll
        for (int b = 0; b < 8; b++) acc[a][b] = 0.f;
    #pragma unroll
    for (int r = 0; r < 32; r++) {
        float qv[8], rv[8];
        #pragma unroll
        for (int tk = 0; tk < 8; tk++) qv[tk] = qrs[tg + 8 * tk][r];
        #pragma unroll
        for (int jc = 0; jc < 8; jc++) rv[jc] = Rst[r][jl + 32 * jc];
        #pragma unroll
        for (int tk = 0; tk < 8; tk++)
            #pragma unroll
            for (int jc = 0; jc < 8; jc++) acc[tk][jc] += qv[tk] * rv[jc];
    }
    #pragma unroll
    for (int tk = 0; tk < 8; tk++) {
        int t = tg + 8 * tk;
        float qb = g_qb[bi * TT + t];
        size_t base = ((size_t)bi * TT + t) * NN;
        #pragma unroll
        for (int jc = 0; jc < 8; jc++)
            g_S[base + jl + 32 * jc] = acc[tk][jc] + qb;
    }
}

// --------------------------------------------- P3: S += q.k^T  (per (b,t), NT)
__global__ __launch_bounds__(256, 2) void k_p3() {
    __shared__ float As[128][20];
    __shared__ float Bs[16][132];
    const int tid = threadIdx.x;
    const int bt = blockIdx.y;
    const int i0 = (blockIdx.x & 1) * 128;
    const int j0 = (blockIdx.x >> 1) * 128;
    const float* Aa = g_qT + (size_t)bt * (NN * 128) + (size_t)i0 * 128;
    const float* Bb = g_kT + (size_t)bt * (NN * 128) + (size_t)j0 * 128;
    const int tx = tid & 15, ty = tid >> 4;
    ull acc2[8][4];
    #pragma unroll
    for (int i = 0; i < 8; i++)
        #pragma unroll
        for (int p = 0; p < 4; p++) acc2[i][p] = 0ull;
    const int lr = tid >> 2;
    const int lk = (tid & 3) * 4;
    for (int k0 = 0; k0 < 128; k0 += 16) {
        #pragma unroll
        for (int it = 0; it < 2; it++) {
            int row = lr + it * 64;
            float4 av = *(const float4*)(Aa + (size_t)row * 128 + k0 + lk);
            *(float4*)&As[row][lk] = av;
            float4 bv = *(const float4*)(Bb + (size_t)row * 128 + k0 + lk);
            Bs[lk + 0][row] = bv.x; Bs[lk + 1][row] = bv.y;
            Bs[lk + 2][row] = bv.z; Bs[lk + 3][row] = bv.w;
        }
        __syncthreads();
        #pragma unroll
        for (int kk = 0; kk < 16; kk++) {
            const float* brow = &Bs[kk][0];
            float4 b0 = *(const float4*)(brow + tx * 4);
            float4 b1 = *(const float4*)(brow + 64 + tx * 4);
            ull b2[4];
            b2[0] = ((ull*)&b0)[0]; b2[1] = ((ull*)&b0)[1];
            b2[2] = ((ull*)&b1)[0]; b2[3] = ((ull*)&b1)[1];
            #pragma unroll
            for (int i = 0; i < 8; i++) {
                ull a2 = dup2(As[ty * 8 + i][kk]);
                fma2(acc2[i][0], a2, b2[0]);
                fma2(acc2[i][1], a2, b2[1]);
                fma2(acc2[i][2], a2, b2[2]);
                fma2(acc2[i][3], a2, b2[3]);
            }
        }
        __syncthreads();
    }
    const int b = bt >> 6, t = bt & 63;
    #pragma unroll
    for (int i = 0; i < 8; i++) {
        int irow = i0 + ty * 8 + i;
        size_t base = ((size_t)((b * NN + irow) * TT + t)) * NN + j0;
        float v[8];
        #pragma unroll
        for (int p = 0; p < 4; p++) {
            float2 f = unpk(acc2[i][p]);
            v[p * 2] = f.x; v[p * 2 + 1] = f.y;
        }
        #pragma unroll
        for (int g = 0; g < 2; g++) {
            int cc = g * 64 + tx * 4;
            float4 o = *(float4*)(g_S + base + cc);
            o.x += v[g*4+0]; o.y += v[g*4+1];
            o.z += v[g*4+2]; o.w += v[g*4+3];
            *(float4*)(g_S + base + cc) = o;
        }
    }
}

// --------------------------------------------- P4a: softmax over t, mask, wsum
__global__ __launch_bounds__(256) void k_p4a() {
    const int bi = blockIdx.x;
    const int i = bi & 255;
    const int j = threadIdx.x;
    size_t base = (size_t)bi * (TT * NN) + j;
    float v[64];
    float mx = -1e30f;
    #pragma unroll
    for (int t = 0; t < 64; t++) { v[t] = g_S[base + t * NN]; mx = fmaxf(mx, v[t]); }
    float s = 0.f;
    #pragma unroll
    for (int t = 0; t < 64; t++) { v[t] = __expf(v[t] - mx); s += v[t]; }
    float inv = (j == i) ? 0.f : (1.f / s);
    #pragma unroll
    for (int t = 0; t < 64; t++) { v[t] *= inv; g_S[base + t * NN] = v[t]; }
    __shared__ float ws[8][64];
    const int lane = j & 31, wp = j >> 5;
    #pragma unroll
    for (int t = 0; t < 64; t++) {
        float r = v[t];
        r += __shfl_xor_sync(0xffffffffu, r, 16);
        r += __shfl_xor_sync(0xffffffffu, r, 8);
        r += __shfl_xor_sync(0xffffffffu, r, 4);
        r += __shfl_xor_sync(0xffffffffu, r, 2);
        r += __shfl_xor_sync(0xffffffffu, r, 1);
        if (lane == 0) ws[wp][t] = r;
    }
    __syncthreads();
    if (j < 64) {
        float s2 = 0.f;
        #pragma unroll
        for (int w = 0; w < 8; w++) s2 += ws[w][j];
        g_wsum[bi * TT + j] = s2;
    }
}

// ------------------------------- P4b: WR = w.R ; P = A'*wsum + WR@W3^T
__global__ __launch_bounds__(256) void k_p4b(const float* __restrict__ R,
                                             const float* __restrict__ Wf) {
    __shared__ float wj[64][72];
    __shared__ float Rs[64][36];
    __shared__ float WRs[64][32];
    __shared__ float wsum_s[64];
    const int bi = blockIdx.x;
    const int tid = threadIdx.x;
    const int rq = tid & 7, tq = tid >> 3;     // tq 0..31; t in {tq, tq+32}
    float a00 = 0.f, a01 = 0.f, a02 = 0.f, a03 = 0.f;
    float a10 = 0.f, a11 = 0.f, a12 = 0.f, a13 = 0.f;
    for (int jc = 0; jc < 4; jc++) {
        const int j0 = jc * 64;
        #pragma unroll
        for (int it = 0; it < 4; it++) {
            int id = tid + it * 256;
            int t = id >> 4, j4 = (id & 15) * 4;
            float4 v = *(const float4*)(g_S + (size_t)bi * (TT * NN) + (size_t)t * NN + j0 + j4);
            *(float4*)&wj[t][j4] = v;
        }
        #pragma unroll
        for (int it = 0; it < 2; it++) {
            int id = tid + it * 256;
            int jj = id >> 3, rr4 = (id & 7) * 4;
            float4 v = *(const float4*)(R + ((size_t)bi * NN + j0 + jj) * DRR + rr4);
            *(float4*)&Rs[jj][rr4] = v;
        }
        __syncthreads();
        #pragma unroll 8
        for (int jj = 0; jj < 64; jj++) {
            float4 rv = *(float4*)&Rs[jj][rq * 4];
            float w0 = wj[tq][jj];
            float w1 = wj[tq + 32][jj];
            a00 += w0 * rv.x; a01 += w0 * rv.y; a02 += w0 * rv.z; a03 += w0 * rv.w;
            a10 += w1 * rv.x; a11 += w1 * rv.y; a12 += w1 * rv.z; a13 += w1 * rv.w;
        }
        __syncthreads();
    }
    *(float4*)&WRs[tq][rq * 4]      = make_float4(a00, a01, a02, a03);
    *(float4*)&WRs[tq + 32][rq * 4] = make_float4(a10, a11, a12, a13);
    if (tid < 64) wsum_s[tid] = g_wsum[bi * TT + tid];
    __syncthreads();
    // phase 2: P[t][e] = Ap[t][e]*wsum[t] + sum_r WRs[t][r]*W3[e][r]
    const int e = tid & 127, th = tid >> 7;
    float w3r[32];
    #pragma unroll
    for (int q = 0; q < 8; q++) {
        float4 v = *(const float4*)(Wf + (size_t)e * 416 + 256 + q * 4);
        w3r[q*4+0] = v.x; w3r[q*4+1] = v.y; w3r[q*4+2] = v.z; w3r[q*4+3] = v.w;
    }
    #pragma unroll 4
    for (int tt = 0; tt < 32; tt++) {
        int t = th * 32 + tt;
        size_t idx = ((size_t)bi * TT + t) * 128 + e;
        float acc = g_Ap[idx] * wsum_s[t];
        #pragma unroll
        for (int q = 0; q < 8; q++) {
            float4 wr = *(float4*)&WRs[t][q * 4];
            acc += wr.x * w3r[q*4+0] + wr.y * w3r[q*4+1]
                 + wr.z * w3r[q*4+2] + wr.w * w3r[q*4+3];
        }
        g_P[idx] = acc;
    }
}

// --------------------------------------------- P5: P += w @ Btil (per (b,t), NN)
__global__ __launch_bounds__(256, 2) void k_p5() {
    __shared__ float As[128][20];
    __shared__ float Bs[16][128];
    const int tid = threadIdx.x;
    const int bt = blockIdx.y;
    const int i0 = blockIdx.x * 128;
    const int b = bt >> 6, t = bt & 63;
    const int tx = tid & 15, ty = tid >> 4;
    ull acc2[8][4];
    #pragma unroll
    for (int i = 0; i < 8; i++)
        #pragma unroll
        for (int p = 0; p < 4; p++) acc2[i][p] = 0ull;
    const int lr = tid >> 2;
    const int lk = (tid & 3) * 4;
    for (int k0 = 0; k0 < 256; k0 += 16) {
        #pragma unroll
        for (int it = 0; it < 2; it++) {
            int row = lr + it * 64;
            size_t abase = ((size_t)((b * NN + i0 + row) * TT + t)) * NN;
            float4 av = *(const float4*)(g_S + abase + k0 + lk);
            *(float4*)&As[row][lk] = av;
        }
        #pragma unroll
        for (int it = 0; it < 2; it++) {
            int id = tid + it * 256;
            int kk = id >> 5, e4 = (id & 31) * 4;
            float4 bv = *(const float4*)(g_Bt + (size_t)bt * (NN * 128) + (size_t)(k0 + kk) * 128 + e4);
            *(float4*)&Bs[kk][e4] = bv;
        }
        __syncthreads();
        #pragma unroll
        for (int kk = 0; kk < 16; kk++) {
            const float* brow = &Bs[kk][0];
            float4 b0 = *(const float4*)(brow + tx * 4);
            float4 b1 = *(const float4*)(brow + 64 + tx * 4);
            ull b2[4];
            b2[0] = ((ull*)&b0)[0]; b2[1] = ((ull*)&b0)[1];
            b2[2] = ((ull*)&b1)[0]; b2[3] = ((ull*)&b1)[1];
            #pragma unroll
            for (int i = 0; i < 8; i++) {
                ull a2 = dup2(As[ty * 8 + i][kk]);
                fma2(acc2[i][0], a2, b2[0]);
                fma2(acc2[i][1], a2, b2[1]);
                fma2(acc2[i][2], a2, b2[2]);
                fma2(acc2[i][3], a2, b2[3]);
            }
        }
        __syncthreads();
    }
    #pragma unroll
    for (int i = 0; i < 8; i++) {
        int irow = i0 + ty * 8 + i;
        size_t base = ((size_t)((b * NN + irow) * TT + t)) * 128;
        float v[8];
        #pragma unroll
        for (int p = 0; p < 4; p++) {
            float2 f = unpk(acc2[i][p]);
            v[p * 2] = f.x; v[p * 2 + 1] = f.y;
        }
        #pragma unroll
        for (int g = 0; g < 2; g++) {
            int cc = g * 64 + tx * 4;
            float4 o = *(float4*)(g_P + base + cc);
            o.x += v[g*4+0]; o.y += v[g*4+1];
            o.z += v[g*4+2]; o.w += v[g*4+3];
            *(float4*)(g_P + base + cc) = o;
        }
    }
}

// --------------------------------------------- P6: layernorm
__global__ __launch_bounds__(128) void k_p6(const float* __restrict__ Hm,
                                            const float* __restrict__ gamma,
                                            const float* __restrict__ beta,
                                            float* __restrict__ out) {
    const int row = blockIdx.x;
    const int d = threadIdx.x;
    size_t idx = (size_t)row * 128 + d;
    float x = Hm[idx] + g_P[idx];
    __shared__ float sm[4], sm2[4];
    float v = x;
    #pragma unroll
    for (int o = 16; o > 0; o >>= 1) v += __shfl_xor_sync(0xffffffffu, v, o);
    if ((d & 31) == 0) sm[d >> 5] = v;
    __syncthreads();
    float mu = (sm[0] + sm[1] + sm[2] + sm[3]) * (1.f / 128.f);
    float dx = x - mu;
    v = dx * dx;
    #pragma unroll
    for (int o = 16; o > 0; o >>= 1) v += __shfl_xor_sync(0xffffffffu, v, o);
    if ((d & 31) == 0) sm2[d >> 5] = v;
    __syncthreads();
    float var = (sm2[0] + sm2[1] + sm2[2] + sm2[3]) * (1.f / 128.f);
    out[idx] = dx * rsqrtf(var + 1e-5f) * gamma[d] + beta[d];
}

// ---------------------------------------------------------------------------
extern "C" void kernel_launch(void* const* d_in, const int* in_sizes, int n_in,
                              void* d_out, int out_size) {
    const float* H     = (const float*)d_in[0];
    const float* R     = (const float*)d_in[1];
    const float* dH    = (const float*)d_in[2];
    const float* Wq    = (const float*)d_in[3];
    const float* bq    = (const float*)d_in[4];
    const float* Wk    = (const float*)d_in[5];
    const float* bk    = (const float*)d_in[6];
    const float* Wr    = (const float*)d_in[7];
    const float* br    = (const float*)d_in[8];
    const float* Wf    = (const float*)d_in[9];
    const float* bf    = (const float*)d_in[10];
    const float* gamma = (const float*)d_in[11];
    const float* beta  = (const float*)d_in[12];
    float* out = (float*)d_out;

    k_prep<<<NCOL + 1, 128>>>(Wq, bq, Wk, bk, Wr, br, Wf, bf);
    k_ej<<<BB * NN, 128>>>(dH, Wf);
    k_qb<<<BB * NN * TT, 128>>>(H);
    k_p1<<<dim3(512, 5), 256>>>(H);
    k_p2<<<BB * NN, 256>>>(R);
    k_p3<<<dim3(4, BB * TT), 256>>>();
    k_p4a<<<BB * NN, 256>>>();
    k_p4b<<<BB * NN, 256>>>(R, Wf);
    k_p5<<<dim3(2, BB * TT), 256>>>();
    k_p6<<<BB * NN * TT, 128>>>(H, gamma, beta, out);
}

// round 9
// speedup vs baseline: 1.2721x; 1.1294x over previous
#include <cuda_runtime.h>
#include <math.h>

// ---------------------------------------------------------------------------
// TemporalCausalAttention  B=4 N=256 T=64 D=128 DR=32 DH=128
// R9: k-major A tiles (vector LDS.128 A-frags) in p1/p3/p5;
//     qr/qb computed from qT (kills p1's 17% wasted block + k_qb).
// ---------------------------------------------------------------------------

#define BB   4
#define NN   256
#define TT   64
#define DD   128
#define DRR  32
#define NCOL 544
#define RSX  0.08838834764831844f   // 1/sqrt(128)

typedef unsigned long long ull;
__device__ __forceinline__ void fma2(ull &c, ull a, ull b) {
    asm("fma.rn.f32x2 %0, %1, %2, %0;" : "+l"(c) : "l"(a), "l"(b));
}
__device__ __forceinline__ ull dup2(float x) {
    ull r; asm("mov.b64 %0, {%1, %1};" : "=l"(r) : "f"(x)); return r;
}
__device__ __forceinline__ float2 unpk(ull v) {
    float2 f; asm("mov.b64 {%0, %1}, %2;" : "=f"(f.x), "=f"(f.y) : "l"(v)); return f;
}

__device__ __align__(16) float g_Wp[NCOL * 128];
__device__ float g_bp[NCOL];
__device__ __align__(16) float g_Ej[BB * NN * DD];
__device__ float g_qb[BB * NN * TT];
__device__ __align__(16) float g_qT[BB * TT * NN * DD];   // (b,t,n,h)
__device__ __align__(16) float g_kT[BB * TT * NN * DD];   // (b,t,n,h)
__device__ __align__(16) float g_Ap[BB * NN * TT * DD];   // (b,n,t,e)  A+bf
__device__ __align__(16) float g_Bt[BB * TT * NN * DD];   // (b,t,n,e)  H@W2+Ej
__device__ __align__(16) float g_qr[BB * NN * TT * DRR];  // (b,n,t,r)
__device__ __align__(16) float g_S [BB * NN * TT * NN];   // (b,i,t,j) scores->w
__device__ __align__(16) float g_P [BB * NN * TT * DD];   // (b,n,t,e)
__device__ float g_wsum[BB * NN * TT];

// --------------------------------------------------------------- weight prep
__global__ void k_prep(const float* __restrict__ Wq, const float* __restrict__ bq,
                       const float* __restrict__ Wk, const float* __restrict__ bk,
                       const float* __restrict__ Wf, const float* __restrict__ bf) {
    const int c = blockIdx.x, d = threadIdx.x;   // c < 512
    float w = 0.f, bias = 0.f;
    if (c < 128)       { w = Wq[c*128 + d] * RSX;           bias = bq[c] * RSX; }
    else if (c < 256)  { int h = c-128; w = Wk[h*128 + d];  bias = bk[h]; }
    else if (c < 384)  { int e = c-256; w = Wf[e*416 + d];  bias = bf[e]; }
    else               { int e = c-384; w = Wf[e*416 + 128 + d]; bias = 0.f; }
    g_Wp[c*128 + d] = w;
    if (d == 0) g_bp[c] = bias;
}

// ------------------------------------------------------------------------ Ej
__global__ void k_ej(const float* __restrict__ dH, const float* __restrict__ Wf) {
    const int bn = blockIdx.x;        // b*256+n
    const int d  = threadIdx.x;       // 128
    __shared__ float ds[128];
    float s = 0.f;
    const float* p = dH + (size_t)bn * TT * DD + d;
    #pragma unroll 8
    for (int t = 0; t < TT; t++) s += p[t * DD];
    ds[d] = s;
    __syncthreads();
    float acc = 0.f;
    const float* w4 = Wf + (size_t)d * 416 + 288;   // W4 row e=d
    #pragma unroll 8
    for (int dd = 0; dd < 128; dd++) acc += ds[dd] * w4[dd];
    g_Ej[(size_t)bn * 128 + d] = acc;
}

// --------------------------------------------- P1: fused projection GEMM (NT)
__global__ __launch_bounds__(256, 2) void k_p1(const float* __restrict__ Hm) {
    __shared__ float As[16][132];   // k-major
    __shared__ float Bs[16][132];   // k-major
    __shared__ float bias_s[128];
    const int tid = threadIdx.x;
    const int r0 = blockIdx.x * 128;
    const int c0 = blockIdx.y * 128;              // c0 < 512, no bounds checks
    const int tx = tid & 15, ty = tid >> 4;
    if (tid < 128) bias_s[tid] = g_bp[c0 + tid];
    ull acc2[8][4];
    #pragma unroll
    for (int i = 0; i < 8; i++)
        #pragma unroll
        for (int p = 0; p < 4; p++) acc2[i][p] = 0ull;
    const int lr = tid >> 2;
    const int lk = (tid & 3) * 4;
    for (int k0 = 0; k0 < 128; k0 += 16) {
        #pragma unroll
        for (int it = 0; it < 2; it++) {
            int row = lr + it * 64;
            float4 av = *(const float4*)(Hm + (size_t)(r0 + row) * 128 + k0 + lk);
            As[lk + 0][row] = av.x; As[lk + 1][row] = av.y;
            As[lk + 2][row] = av.z; As[lk + 3][row] = av.w;
            float4 bv = *(const float4*)(g_Wp + (size_t)(c0 + row) * 128 + k0 + lk);
            Bs[lk + 0][row] = bv.x; Bs[lk + 1][row] = bv.y;
            Bs[lk + 2][row] = bv.z; Bs[lk + 3][row] = bv.w;
        }
        __syncthreads();
        #pragma unroll
        for (int kk = 0; kk < 16; kk++) {
            float4 a0 = *(const float4*)&As[kk][ty * 8];
            float4 a1 = *(const float4*)&As[kk][ty * 8 + 4];
            float4 b0 = *(const float4*)&Bs[kk][tx * 4];
            float4 b1 = *(const float4*)&Bs[kk][64 + tx * 4];
            ull b2[4];
            b2[0] = ((ull*)&b0)[0]; b2[1] = ((ull*)&b0)[1];
            b2[2] = ((ull*)&b1)[0]; b2[3] = ((ull*)&b1)[1];
            float av8[8] = {a0.x, a0.y, a0.z, a0.w, a1.x, a1.y, a1.z, a1.w};
            #pragma unroll
            for (int i = 0; i < 8; i++) {
                ull a2 = dup2(av8[i]);
                fma2(acc2[i][0], a2, b2[0]);
                fma2(acc2[i][1], a2, b2[1]);
                fma2(acc2[i][2], a2, b2[2]);
                fma2(acc2[i][3], a2, b2[3]);
            }
        }
        __syncthreads();
    }
    #pragma unroll
    for (int i = 0; i < 8; i++) {
        int r = r0 + ty * 8 + i;
        int b = r >> 14, n = (r >> 6) & 255, t = r & 63;
        size_t tb = ((size_t)((b * TT + t) * NN + n)) * 128;
        float v[8];
        #pragma unroll
        for (int p = 0; p < 4; p++) {
            float2 f = unpk(acc2[i][p]);
            v[p * 2] = f.x; v[p * 2 + 1] = f.y;
        }
        #pragma unroll
        for (int g = 0; g < 2; g++) {
            int c = c0 + g * 64 + tx * 4;
            int bs = g * 64 + tx * 4;
            float v0 = v[g*4+0] + bias_s[bs+0];
            float v1 = v[g*4+1] + bias_s[bs+1];
            float v2 = v[g*4+2] + bias_s[bs+2];
            float v3 = v[g*4+3] + bias_s[bs+3];
            if (c < 128) {
                *(float4*)(g_qT + tb + c) = make_float4(v0, v1, v2, v3);
            } else if (c < 256) {
                *(float4*)(g_kT + tb + (c - 128)) = make_float4(v0, v1, v2, v3);
            } else if (c < 384) {
                *(float4*)(g_Ap + (size_t)r * 128 + (c - 256)) = make_float4(v0, v1, v2, v3);
            } else {
                const float* ej = g_Ej + (size_t)(b * NN + n) * 128 + (c - 384);
                *(float4*)(g_Bt + tb + (c - 384)) =
                    make_float4(v0 + ej[0], v1 + ej[1], v2 + ej[2], v3 + ej[3]);
            }
        }
    }
}

// --------------------------------- qr = qT @ Wr ; qb = qT . br   (per bi,t-half)
__global__ __launch_bounds__(256) void k_qr(const float* __restrict__ Wr,
                                            const float* __restrict__ br) {
    __shared__ float qs[32][132];
    __shared__ float Ws[128][36];
    __shared__ float brs[128];
    const int bi = blockIdx.y;                 // b*256+i
    const int b = bi >> 8, i = bi & 255;
    const int t0 = blockIdx.x * 32;
    const int tid = threadIdx.x;
    // q slice: 32 t-rows x 128 h  (rows contiguous in qT)
    #pragma unroll
    for (int it = 0; it < 4; it++) {
        int id = tid + it * 256;               // 0..1023
        int trow = id >> 5, h4 = (id & 31) * 4;
        float4 v = *(const float4*)(g_qT +
            ((size_t)((b * TT + t0 + trow) * NN + i)) * 128 + h4);
        *(float4*)&qs[trow][h4] = v;
    }
    // Wr: [128][32] -> Ws[h][r]
    #pragma unroll
    for (int it = 0; it < 4; it++) {
        int id = tid + it * 256;               // 0..1023
        int h = id >> 3, r4 = (id & 7) * 4;
        float4 v = *(const float4*)(Wr + (size_t)h * 32 + r4);
        *(float4*)&Ws[h][r4] = v;
    }
    if (tid < 128) brs[tid] = br[tid];
    __syncthreads();
    const int tt = tid >> 3, rg = tid & 7;     // tt 0..31, rg 0..7
    ull acc[2] = {0ull, 0ull};
    #pragma unroll 8
    for (int h = 0; h < 128; h++) {
        ull a2 = dup2(qs[tt][h]);
        float4 w = *(const float4*)&Ws[h][rg * 4];
        fma2(acc[0], a2, ((ull*)&w)[0]);
        fma2(acc[1], a2, ((ull*)&w)[1]);
    }
    float2 f0 = unpk(acc[0]), f1 = unpk(acc[1]);
    *(float4*)(g_qr + ((size_t)bi * TT + t0 + tt) * DRR + rg * 4) =
        make_float4(f0.x, f0.y, f1.x, f1.y);
    if (rg == 0) {
        float s = 0.f;
        #pragma unroll 8
        for (int h = 0; h < 128; h++) s += qs[tt][h] * brs[h];
        g_qb[bi * TT + t0 + tt] = s;
    }
}

// --------------------------------------------- P2: S init = qr.R + qb
__global__ __launch_bounds__(256) void k_p2(const float* __restrict__ R) {
    __shared__ float qrs[64][36];
    __shared__ float Rst[32][265];
    const int bi = blockIdx.x;
    const int tid = threadIdx.x;
    #pragma unroll
    for (int it = 0; it < 2; it++) {
        int id = tid + it * 256;
        int t = id >> 3, rq = (id & 7) * 4;
        float4 v = *(const float4*)(g_qr + (size_t)bi * (TT * DRR) + t * DRR + rq);
        *(float4*)&qrs[t][rq] = v;
    }
    #pragma unroll
    for (int it = 0; it < 8; it++) {
        int id = tid + it * 256;                 // 0..2047
        int j = id >> 3, rq = (id & 7) * 4;
        float4 v = *(const float4*)(R + (size_t)bi * (NN * DRR) + (size_t)j * DRR + rq);
        Rst[rq + 0][j] = v.x; Rst[rq + 1][j] = v.y;
        Rst[rq + 2][j] = v.z; Rst[rq + 3][j] = v.w;
    }
    __syncthreads();
    const int jl = tid & 31, tg = tid >> 5;
    float acc[8][8];
    #pragma unroll
    for (int a = 0; a < 8; a++)
        #pragma unroll
        for (int b = 0; b < 8; b++) acc[a][b] = 0.f;
    #pragma unroll
    for (int r = 0; r < 32; r++) {
        float qv[8], rv[8];
        #pragma unroll
        for (int tk = 0; tk < 8; tk++) qv[tk] = qrs[tg + 8 * tk][r];
        #pragma unroll
        for (int jc = 0; jc < 8; jc++) rv[jc] = Rst[r][jl + 32 * jc];
        #pragma unroll
        for (int tk = 0; tk < 8; tk++)
            #pragma unroll
            for (int jc = 0; jc < 8; jc++) acc[tk][jc] += qv[tk] * rv[jc];
    }
    #pragma unroll
    for (int tk = 0; tk < 8; tk++) {
        int t = tg + 8 * tk;
        float qb = g_qb[bi * TT + t];
        size_t base = ((size_t)bi * TT + t) * NN;
        #pragma unroll
        for (int jc = 0; jc < 8; jc++)
            g_S[base + jl + 32 * jc] = acc[tk][jc] + qb;
    }
}

// --------------------------------------------- P3: S += q.k^T  (per (b,t), NT)
__global__ __launch_bounds__(256, 2) void k_p3() {
    __shared__ float As[16][132];
    __shared__ float Bs[16][132];
    const int tid = threadIdx.x;
    const int bt = blockIdx.y;
    const int i0 = (blockIdx.x & 1) * 128;
    const int j0 = (blockIdx.x >> 1) * 128;
    const float* Aa = g_qT + (size_t)bt * (NN * 128) + (size_t)i0 * 128;
    const float* Bb = g_kT + (size_t)bt * (NN * 128) + (size_t)j0 * 128;
    const int tx = tid & 15, ty = tid >> 4;
    ull acc2[8][4];
    #pragma unroll
    for (int i = 0; i < 8; i++)
        #pragma unroll
        for (int p = 0; p < 4; p++) acc2[i][p] = 0ull;
    const int lr = tid >> 2;
    const int lk = (tid & 3) * 4;
    for (int k0 = 0; k0 < 128; k0 += 16) {
        #pragma unroll
        for (int it = 0; it < 2; it++) {
            int row = lr + it * 64;
            float4 av = *(const float4*)(Aa + (size_t)row * 128 + k0 + lk);
            As[lk + 0][row] = av.x; As[lk + 1][row] = av.y;
            As[lk + 2][row] = av.z; As[lk + 3][row] = av.w;
            float4 bv = *(const float4*)(Bb + (size_t)row * 128 + k0 + lk);
            Bs[lk + 0][row] = bv.x; Bs[lk + 1][row] = bv.y;
            Bs[lk + 2][row] = bv.z; Bs[lk + 3][row] = bv.w;
        }
        __syncthreads();
        #pragma unroll
        for (int kk = 0; kk < 16; kk++) {
            float4 a0 = *(const float4*)&As[kk][ty * 8];
            float4 a1 = *(const float4*)&As[kk][ty * 8 + 4];
            float4 b0 = *(const float4*)&Bs[kk][tx * 4];
            float4 b1 = *(const float4*)&Bs[kk][64 + tx * 4];
            ull b2[4];
            b2[0] = ((ull*)&b0)[0]; b2[1] = ((ull*)&b0)[1];
            b2[2] = ((ull*)&b1)[0]; b2[3] = ((ull*)&b1)[1];
            float av8[8] = {a0.x, a0.y, a0.z, a0.w, a1.x, a1.y, a1.z, a1.w};
            #pragma unroll
            for (int i = 0; i < 8; i++) {
                ull a2 = dup2(av8[i]);
                fma2(acc2[i][0], a2, b2[0]);
                fma2(acc2[i][1], a2, b2[1]);
                fma2(acc2[i][2], a2, b2[2]);
                fma2(acc2[i][3], a2, b2[3]);
            }
        }
        __syncthreads();
    }
    const int b = bt >> 6, t = bt & 63;
    #pragma unroll
    for (int i = 0; i < 8; i++) {
        int irow = i0 + ty * 8 + i;
        size_t base = ((size_t)((b * NN + irow) * TT + t)) * NN + j0;
        float v[8];
        #pragma unroll
        for (int p = 0; p < 4; p++) {
            float2 f = unpk(acc2[i][p]);
            v[p * 2] = f.x; v[p * 2 + 1] = f.y;
        }
        #pragma unroll
        for (int g = 0; g < 2; g++) {
            int cc = g * 64 + tx * 4;
            float4 o = *(float4*)(g_S + base + cc);
            o.x += v[g*4+0]; o.y += v[g*4+1];
            o.z += v[g*4+2]; o.w += v[g*4+3];
            *(float4*)(g_S + base + cc) = o;
        }
    }
}

// --------------------------------------------- P4a: softmax over t, mask, wsum
__global__ __launch_bounds__(256) void k_p4a() {
    const int bi = blockIdx.x;
    const int i = bi & 255;
    const int j = threadIdx.x;
    size_t base = (size_t)bi * (TT * NN) + j;
    float v[64];
    float mx = -1e30f;
    #pragma unroll
    for (int t = 0; t < 64; t++) { v[t] = g_S[base + t * NN]; mx = fmaxf(mx, v[t]); }
    float s = 0.f;
    #pragma unroll
    for (int t = 0; t < 64; t++) { v[t] = __expf(v[t] - mx); s += v[t]; }
    float inv = (j == i) ? 0.f : (1.f / s);
    #pragma unroll
    for (int t = 0; t < 64; t++) { v[t] *= inv; g_S[base + t * NN] = v[t]; }
    __shared__ float ws[8][64];
    const int lane = j & 31, wp = j >> 5;
    #pragma unroll
    for (int t = 0; t < 64; t++) {
        float r = v[t];
        r += __shfl_xor_sync(0xffffffffu, r, 16);
        r += __shfl_xor_sync(0xffffffffu, r, 8);
        r += __shfl_xor_sync(0xffffffffu, r, 4);
        r += __shfl_xor_sync(0xffffffffu, r, 2);
        r += __shfl_xor_sync(0xffffffffu, r, 1);
        if (lane == 0) ws[wp][t] = r;
    }
    __syncthreads();
    if (j < 64) {
        float s2 = 0.f;
        #pragma unroll
        for (int w = 0; w < 8; w++) s2 += ws[w][j];
        g_wsum[bi * TT + j] = s2;
    }
}

// ------------------------------- P4b: WR = w.R ; P = A'*wsum + WR@W3^T
__global__ __launch_bounds__(256) void k_p4b(const float* __restrict__ R,
                                             const float* __restrict__ Wf) {
    __shared__ float wj[64][72];
    __shared__ float Rs[64][36];
    __shared__ float WRs[64][32];
    __shared__ float wsum_s[64];
    const int bi = blockIdx.x;
    const int tid = threadIdx.x;
    const int rq = tid & 7, tq = tid >> 3;     // tq 0..31; t in {tq, tq+32}
    float a00 = 0.f, a01 = 0.f, a02 = 0.f, a03 = 0.f;
    float a10 = 0.f, a11 = 0.f, a12 = 0.f, a13 = 0.f;
    for (int jc = 0; jc < 4; jc++) {
        const int j0 = jc * 64;
        #pragma unroll
        for (int it = 0; it < 4; it++) {
            int id = tid + it * 256;
            int t = id >> 4, j4 = (id & 15) * 4;
            float4 v = *(const float4*)(g_S + (size_t)bi * (TT * NN) + (size_t)t * NN + j0 + j4);
            *(float4*)&wj[t][j4] = v;
        }
        #pragma unroll
        for (int it = 0; it < 2; it++) {
            int id = tid + it * 256;
            int jj = id >> 3, rr4 = (id & 7) * 4;
            float4 v = *(const float4*)(R + ((size_t)bi * NN + j0 + jj) * DRR + rr4);
            *(float4*)&Rs[jj][rr4] = v;
        }
        __syncthreads();
        #pragma unroll 8
        for (int jj = 0; jj < 64; jj++) {
            float4 rv = *(float4*)&Rs[jj][rq * 4];
            float w0 = wj[tq][jj];
            float w1 = wj[tq + 32][jj];
            a00 += w0 * rv.x; a01 += w0 * rv.y; a02 += w0 * rv.z; a03 += w0 * rv.w;
            a10 += w1 * rv.x; a11 += w1 * rv.y; a12 += w1 * rv.z; a13 += w1 * rv.w;
        }
        __syncthreads();
    }
    *(float4*)&WRs[tq][rq * 4]      = make_float4(a00, a01, a02, a03);
    *(float4*)&WRs[tq + 32][rq * 4] = make_float4(a10, a11, a12, a13);
    if (tid < 64) wsum_s[tid] = g_wsum[bi * TT + tid];
    __syncthreads();
    // phase 2: P[t][e] = Ap[t][e]*wsum[t] + sum_r WRs[t][r]*W3[e][r]
    const int e = tid & 127, th = tid >> 7;
    float w3r[32];
    #pragma unroll
    for (int q = 0; q < 8; q++) {
        float4 v = *(const float4*)(Wf + (size_t)e * 416 + 256 + q * 4);
        w3r[q*4+0] = v.x; w3r[q*4+1] = v.y; w3r[q*4+2] = v.z; w3r[q*4+3] = v.w;
    }
    #pragma unroll 4
    for (int tt = 0; tt < 32; tt++) {
        int t = th * 32 + tt;
        size_t idx = ((size_t)bi * TT + t) * 128 + e;
        float acc = g_Ap[idx] * wsum_s[t];
        #pragma unroll
        for (int q = 0; q < 8; q++) {
            float4 wr = *(float4*)&WRs[t][q * 4];
            acc += wr.x * w3r[q*4+0] + wr.y * w3r[q*4+1]
                 + wr.z * w3r[q*4+2] + wr.w * w3r[q*4+3];
        }
        g_P[idx] = acc;
    }
}

// --------------------------------------------- P5: P += w @ Btil (per (b,t), NN)
__global__ __launch_bounds__(256, 2) void k_p5() {
    __shared__ float As[16][132];
    __shared__ float Bs[16][128];
    const int tid = threadIdx.x;
    const int bt = blockIdx.y;
    const int i0 = blockIdx.x * 128;
    const int b = bt >> 6, t = bt & 63;
    const int tx = tid & 15, ty = tid >> 4;
    ull acc2[8][4];
    #pragma unroll
    for (int i = 0; i < 8; i++)
        #pragma unroll
        for (int p = 0; p < 4; p++) acc2[i][p] = 0ull;
    const int lr = tid >> 2;
    const int lk = (tid & 3) * 4;
    for (int k0 = 0; k0 < 256; k0 += 16) {
        #pragma unroll
        for (int it = 0; it < 2; it++) {
            int row = lr + it * 64;
            size_t abase = ((size_t)((b * NN + i0 + row) * TT + t)) * NN;
            float4 av = *(const float4*)(g_S + abase + k0 + lk);
            As[lk + 0][row] = av.x; As[lk + 1][row] = av.y;
            As[lk + 2][row] = av.z; As[lk + 3][row] = av.w;
        }
        #pragma unroll
        for (int it = 0; it < 2; it++) {
            int id = tid + it * 256;
            int kk = id >> 5, e4 = (id & 31) * 4;
            float4 bv = *(const float4*)(g_Bt + (size_t)bt * (NN * 128) + (size_t)(k0 + kk) * 128 + e4);
            *(float4*)&Bs[kk][e4] = bv;
        }
        __syncthreads();
        #pragma unroll
        for (int kk = 0; kk < 16; kk++) {
            float4 a0 = *(const float4*)&As[kk][ty * 8];
            float4 a1 = *(const float4*)&As[kk][ty * 8 + 4];
            float4 b0 = *(const float4*)&Bs[kk][tx * 4];
            float4 b1 = *(const float4*)&Bs[kk][64 + tx * 4];
            ull b2[4];
            b2[0] = ((ull*)&b0)[0]; b2[1] = ((ull*)&b0)[1];
            b2[2] = ((ull*)&b1)[0]; b2[3] = ((ull*)&b1)[1];
            float av8[8] = {a0.x, a0.y, a0.z, a0.w, a1.x, a1.y, a1.z, a1.w};
            #pragma unroll
            for (int i = 0; i < 8; i++) {
                ull a2 = dup2(av8[i]);
                fma2(acc2[i][0], a2, b2[0]);
                fma2(acc2[i][1], a2, b2[1]);
                fma2(acc2[i][2], a2, b2[2]);
                fma2(acc2[i][3], a2, b2[3]);
            }
        }
        __syncthreads();
    }
    #pragma unroll
    for (int i = 0; i < 8; i++) {
        int irow = i0 + ty * 8 + i;
        size_t base = ((size_t)((b * NN + irow) * TT + t)) * 128;
        float v[8];
        #pragma unroll
        for (int p = 0; p < 4; p++) {
            float2 f = unpk(acc2[i][p]);
            v[p * 2] = f.x; v[p * 2 + 1] = f.y;
        }
        #pragma unroll
        for (int g = 0; g < 2; g++) {
            int cc = g * 64 + tx * 4;
            float4 o = *(float4*)(g_P + base + cc);
            o.x += v[g*4+0]; o.y += v[g*4+1];
            o.z += v[g*4+2]; o.w += v[g*4+3];
            *(float4*)(g_P + base + cc) = o;
        }
    }
}

// --------------------------------------------- P6: layernorm
__global__ __launch_bounds__(128) void k_p6(const float* __restrict__ Hm,
                                            const float* __restrict__ gamma,
                                            const float* __restrict__ beta,
                                            float* __restrict__ out) {
    const int row = blockIdx.x;
    const int d = threadIdx.x;
    size_t idx = (size_t)row * 128 + d;
    float x = Hm[idx] + g_P[idx];
    __shared__ float sm[4], sm2[4];
    float v = x;
    #pragma unroll
    for (int o = 16; o > 0; o >>= 1) v += __shfl_xor_sync(0xffffffffu, v, o);
    if ((d & 31) == 0) sm[d >> 5] = v;
    __syncthreads();
    float mu = (sm[0] + sm[1] + sm[2] + sm[3]) * (1.f / 128.f);
    float dx = x - mu;
    v = dx * dx;
    #pragma unroll
    for (int o = 16; o > 0; o >>= 1) v += __shfl_xor_sync(0xffffffffu, v, o);
    if ((d & 31) == 0) sm2[d >> 5] = v;
    __syncthreads();
    float var = (sm2[0] + sm2[1] + sm2[2] + sm2[3]) * (1.f / 128.f);
    out[idx] = dx * rsqrtf(var + 1e-5f) * gamma[d] + beta[d];
}

// ---------------------------------------------------------------------------
extern "C" void kernel_launch(void* const* d_in, const int* in_sizes, int n_in,
                              void* d_out, int out_size) {
    const float* H     = (const float*)d_in[0];
    const float* R     = (const float*)d_in[1];
    const float* dH    = (const float*)d_in[2];
    const float* Wq    = (const float*)d_in[3];
    const float* bq    = (const float*)d_in[4];
    const float* Wk    = (const float*)d_in[5];
    const float* bk    = (const float*)d_in[6];
    const float* Wr    = (const float*)d_in[7];
    const float* br    = (const float*)d_in[8];
    const float* Wf    = (const float*)d_in[9];
    const float* bf    = (const float*)d_in[10];
    const float* gamma = (const float*)d_in[11];
    const float* beta  = (const float*)d_in[12];
    float* out = (float*)d_out;

    k_prep<<<512, 128>>>(Wq, bq, Wk, bk, Wf, bf);
    k_ej<<<BB * NN, 128>>>(dH, Wf);
    k_p1<<<dim3(512, 4), 256>>>(H);
    k_qr<<<dim3(2, BB * NN), 256>>>(Wr, br);
    k_p2<<<BB * NN, 256>>>(R);
    k_p3<<<dim3(4, BB * TT), 256>>>();
    k_p4a<<<BB * NN, 256>>>();
    k_p4b<<<BB * NN, 256>>>(R, Wf);
    k_p5<<<dim3(2, BB * TT), 256>>>();
    k_p6<<<BB * NN * TT, 128>>>(H, gamma, beta, out);
}

// round 16
// speedup vs baseline: 1.2858x; 1.0107x over previous
#include <cuda_runtime.h>
#include <math.h>

// ---------------------------------------------------------------------------
// TemporalCausalAttention  B=4 N=256 T=64 D=128 DR=32 DH=128
// R10 (clean re-emit): k_qr rebuilt as H @ (Wq^T Wr) GEMM (k-major, f32x2).
// Rest identical to the 680us R9 kernel.
// ---------------------------------------------------------------------------

#define BB   4
#define NN   256
#define TT   64
#define DD   128
#define DRR  32
#define NCOL 544
#define RSX  0.08838834764831844f   // 1/sqrt(128)

typedef unsigned long long ull;
__device__ __forceinline__ void fma2(ull &c, ull a, ull b) {
    asm("fma.rn.f32x2 %0, %1, %2, %0;" : "+l"(c) : "l"(a), "l"(b));
}
__device__ __forceinline__ ull dup2(float x) {
    ull r; asm("mov.b64 %0, {%1, %1};" : "=l"(r) : "f"(x)); return r;
}
__device__ __forceinline__ float2 unpk(ull v) {
    float2 f; asm("mov.b64 {%0, %1}, %2;" : "=f"(f.x), "=f"(f.y) : "l"(v)); return f;
}

__device__ __align__(16) float g_Wp[NCOL * 128];
__device__ float g_bp[NCOL];
__device__ __align__(16) float g_WqrP[128 * 36];   // [d][r], col32=wqb, 33-35 pad
__device__ float g_qrb[36];                        // r<32: bq.Wr*rs, [32]=bq.br*rs
__device__ __align__(16) float g_Ej[BB * NN * DD];
__device__ float g_qb[BB * NN * TT];
__device__ __align__(16) float g_qT[BB * TT * NN * DD];   // (b,t,n,h)
__device__ __align__(16) float g_kT[BB * TT * NN * DD];   // (b,t,n,h)
__device__ __align__(16) float g_Ap[BB * NN * TT * DD];   // (b,n,t,e)  A+bf
__device__ __align__(16) float g_Bt[BB * TT * NN * DD];   // (b,t,n,e)  H@W2+Ej
__device__ __align__(16) float g_qr[BB * NN * TT * DRR];  // (b,n,t,r)
__device__ __align__(16) float g_S [BB * NN * TT * NN];   // (b,i,t,j)
__device__ __align__(16) float g_P [BB * NN * TT * DD];   // (b,n,t,e)
__device__ float g_wsum[BB * NN * TT];

// --------------------------------------------------------------- weight prep
__global__ void k_prep(const float* __restrict__ Wq, const float* __restrict__ bq,
                       const float* __restrict__ Wk, const float* __restrict__ bk,
                       const float* __restrict__ Wr, const float* __restrict__ br,
                       const float* __restrict__ Wf, const float* __restrict__ bf) {
    const int c = blockIdx.x, d = threadIdx.x;
    if (c < 512) {
        float w = 0.f, bias = 0.f;
        if (c < 128)       { w = Wq[c*128 + d] * RSX;             bias = bq[c] * RSX; }
        else if (c < 256)  { int h = c-128; w = Wk[h*128 + d];    bias = bk[h]; }
        else if (c < 384)  { int e = c-256; w = Wf[e*416 + d];    bias = bf[e]; }
        else               { int e = c-384; w = Wf[e*416 + 128 + d]; bias = 0.f; }
        g_Wp[c*128 + d] = w;
        if (d == 0) g_bp[c] = bias;
    } else if (c < 544) {                    // Wqr column r = c-512
        int r = c - 512;
        float a = 0.f, bbv = 0.f;
        for (int h = 0; h < 128; h++) {
            a   += Wq[h*128 + d] * Wr[h*32 + r];
            bbv += bq[h]         * Wr[h*32 + r];
        }
        g_WqrP[d*36 + r] = a * RSX;
        if (d == 0) g_qrb[r] = bbv * RSX;
    } else {                                 // c == 544: wqb col + pads
        float a = 0.f;
        for (int h = 0; h < 128; h++) a += Wq[h*128 + d] * br[h];
        g_WqrP[d*36 + 32] = a * RSX;
        g_WqrP[d*36 + 33] = 0.f;
        g_WqrP[d*36 + 34] = 0.f;
        g_WqrP[d*36 + 35] = 0.f;
        if (d == 0) {
            float bbv = 0.f;
            for (int h = 0; h < 128; h++) bbv += bq[h] * br[h];
            g_qrb[32] = bbv * RSX;
            g_qrb[33] = 0.f; g_qrb[34] = 0.f; g_qrb[35] = 0.f;
        }
    }
}

// ------------------------------------------------------------------------ Ej
__global__ void k_ej(const float* __restrict__ dH, const float* __restrict__ Wf) {
    const int bn = blockIdx.x;        // b*256+n
    const int d  = threadIdx.x;       // 128
    __shared__ float ds[128];
    float s = 0.f;
    const float* p = dH + (size_t)bn * TT * DD + d;
    #pragma unroll 8
    for (int t = 0; t < TT; t++) s += p[t * DD];
    ds[d] = s;
    __syncthreads();
    float acc = 0.f;
    const float* w4 = Wf + (size_t)d * 416 + 288;   // W4 row e=d
    #pragma unroll 8
    for (int dd = 0; dd < 128; dd++) acc += ds[dd] * w4[dd];
    g_Ej[(size_t)bn * 128 + d] = acc;
}

// --------------------------------------------- P1: fused projection GEMM (NT)
__global__ __launch_bounds__(256, 2) void k_p1(const float* __restrict__ Hm) {
    __shared__ float As[16][132];
    __shared__ float Bs[16][132];
    __shared__ float bias_s[128];
    const int tid = threadIdx.x;
    const int r0 = blockIdx.x * 128;
    const int c0 = blockIdx.y * 128;              // c0 in {0,128,256,384}
    const int tx = tid & 15, ty = tid >> 4;
    if (tid < 128) bias_s[tid] = g_bp[c0 + tid];
    ull acc2[8][4];
    #pragma unroll
    for (int i = 0; i < 8; i++)
        #pragma unroll
        for (int p = 0; p < 4; p++) acc2[i][p] = 0ull;
    const int lr = tid >> 2;
    const int lk = (tid & 3) * 4;
    for (int k0 = 0; k0 < 128; k0 += 16) {
        #pragma unroll
        for (int it = 0; it < 2; it++) {
            int row = lr + it * 64;
            float4 av = *(const float4*)(Hm + (size_t)(r0 + row) * 128 + k0 + lk);
            As[lk + 0][row] = av.x; As[lk + 1][row] = av.y;
            As[lk + 2][row] = av.z; As[lk + 3][row] = av.w;
            float4 bv = *(const float4*)(g_Wp + (size_t)(c0 + row) * 128 + k0 + lk);
            Bs[lk + 0][row] = bv.x; Bs[lk + 1][row] = bv.y;
            Bs[lk + 2][row] = bv.z; Bs[lk + 3][row] = bv.w;
        }
        __syncthreads();
        #pragma unroll
        for (int kk = 0; kk < 16; kk++) {
            float4 a0 = *(const float4*)&As[kk][ty * 8];
            float4 a1 = *(const float4*)&As[kk][ty * 8 + 4];
            float4 b0 = *(const float4*)&Bs[kk][tx * 4];
            float4 b1 = *(const float4*)&Bs[kk][64 + tx * 4];
            ull b2[4];
            b2[0] = ((ull*)&b0)[0]; b2[1] = ((ull*)&b0)[1];
            b2[2] = ((ull*)&b1)[0]; b2[3] = ((ull*)&b1)[1];
            float av8[8] = {a0.x, a0.y, a0.z, a0.w, a1.x, a1.y, a1.z, a1.w};
            #pragma unroll
            for (int i = 0; i < 8; i++) {
                ull a2 = dup2(av8[i]);
                fma2(acc2[i][0], a2, b2[0]);
                fma2(acc2[i][1], a2, b2[1]);
                fma2(acc2[i][2], a2, b2[2]);
                fma2(acc2[i][3], a2, b2[3]);
            }
        }
        __syncthreads();
    }
    #pragma unroll
    for (int i = 0; i < 8; i++) {
        int r = r0 + ty * 8 + i;
        int b = r >> 14, n = (r >> 6) & 255, t = r & 63;
        size_t tb = ((size_t)((b * TT + t) * NN + n)) * 128;
        float v[8];
        #pragma unroll
        for (int p = 0; p < 4; p++) {
            float2 f = unpk(acc2[i][p]);
            v[p * 2] = f.x; v[p * 2 + 1] = f.y;
        }
        #pragma unroll
        for (int g = 0; g < 2; g++) {
            int c = c0 + g * 64 + tx * 4;
            int bs = g * 64 + tx * 4;
            float v0 = v[g*4+0] + bias_s[bs+0];
            float v1 = v[g*4+1] + bias_s[bs+1];
            float v2 = v[g*4+2] + bias_s[bs+2];
            float v3 = v[g*4+3] + bias_s[bs+3];
            if (c < 128) {
                *(float4*)(g_qT + tb + c) = make_float4(v0, v1, v2, v3);
            } else if (c < 256) {
                *(float4*)(g_kT + tb + (c - 128)) = make_float4(v0, v1, v2, v3);
            } else if (c < 384) {
                *(float4*)(g_Ap + (size_t)r * 128 + (c - 256)) = make_float4(v0, v1, v2, v3);
            } else {
                const float* ej = g_Ej + (size_t)(b * NN + n) * 128 + (c - 384);
                *(float4*)(g_Bt + tb + (c - 384)) =
                    make_float4(v0 + ej[0], v1 + ej[1], v2 + ej[2], v3 + ej[3]);
            }
        }
    }
}

// ---------------- qr/qb GEMM from H: [65536 x 33] = H @ WqrP  (k-major tiles)
__global__ __launch_bounds__(256, 2) void k_qr(const float* __restrict__ Hm) {
    __shared__ float As[16][132];
    __shared__ float Ws[128][36];
    __shared__ float bias_s[36];
    const int tid = threadIdx.x;
    const int r0 = blockIdx.x * 128;
    #pragma unroll
    for (int it = 0; it < 5; it++) {
        int id = tid + it * 256;                 // 128*36/4 = 1152 float4 loads
        if (id < 1152) {
            int row = id / 9, c4 = (id % 9) * 4;
            *(float4*)&Ws[row][c4] = *(const float4*)(g_WqrP + row * 36 + c4);
        }
    }
    if (tid < 36) bias_s[tid] = g_qrb[tid];
    const int tx = tid & 7, ty = tid >> 3;       // tx: 8 r-groups, ty: 32 row-groups
    ull acc2[4][2];
    float qbacc[4] = {0.f, 0.f, 0.f, 0.f};
    #pragma unroll
    for (int i = 0; i < 4; i++) { acc2[i][0] = 0ull; acc2[i][1] = 0ull; }
    const int lr = tid >> 2;
    const int lk = (tid & 3) * 4;
    for (int k0 = 0; k0 < 128; k0 += 16) {
        #pragma unroll
        for (int it = 0; it < 2; it++) {
            int row = lr + it * 64;
            float4 av = *(const float4*)(Hm + (size_t)(r0 + row) * 128 + k0 + lk);
            As[lk + 0][row] = av.x; As[lk + 1][row] = av.y;
            As[lk + 2][row] = av.z; As[lk + 3][row] = av.w;
        }
        __syncthreads();
        #pragma unroll
        for (int kk = 0; kk < 16; kk++) {
            float4 a = *(const float4*)&As[kk][ty * 4];
            float4 w = *(const float4*)&Ws[k0 + kk][tx * 4];
            ull w2[2];
            w2[0] = ((ull*)&w)[0]; w2[1] = ((ull*)&w)[1];
            float av4[4] = {a.x, a.y, a.z, a.w};
            #pragma unroll
            for (int i = 0; i < 4; i++) {
                ull a2 = dup2(av4[i]);
                fma2(acc2[i][0], a2, w2[0]);
                fma2(acc2[i][1], a2, w2[1]);
            }
            if (tx == 0) {
                float wqbv = Ws[k0 + kk][32];
                #pragma unroll
                for (int i = 0; i < 4; i++) qbacc[i] += av4[i] * wqbv;
            }
        }
        __syncthreads();
    }
    #pragma unroll
    for (int i = 0; i < 4; i++) {
        int r = r0 + ty * 4 + i;                 // global H row = (b,n,t) flat
        float2 f0 = unpk(acc2[i][0]), f1 = unpk(acc2[i][1]);
        *(float4*)(g_qr + (size_t)r * DRR + tx * 4) = make_float4(
            f0.x + bias_s[tx*4+0], f0.y + bias_s[tx*4+1],
            f1.x + bias_s[tx*4+2], f1.y + bias_s[tx*4+3]);
        if (tx == 0) g_qb[r] = qbacc[i] + bias_s[32];
    }
}

// --------------------------------------------- P2: S init = qr.R + qb
__global__ __launch_bounds__(256) void k_p2(const float* __restrict__ R) {
    __shared__ float qrs[64][36];
    __shared__ float Rst[32][265];
    const int bi = blockIdx.x;
    const int tid = threadIdx.x;
    #pragma unroll
    for (int it = 0; it < 2; it++) {
        int id = tid + it * 256;
        int t = id >> 3, rq = (id & 7) * 4;
        float4 v = *(const float4*)(g_qr + (size_t)bi * (TT * DRR) + t * DRR + rq);
        *(float4*)&qrs[t][rq] = v;
    }
    #pragma unroll
    for (int it = 0; it < 8; it++) {
        int id = tid + it * 256;                 // 0..2047
        int j = id >> 3, rq = (id & 7) * 4;
        float4 v = *(const float4*)(R + (size_t)bi * (NN * DRR) + (size_t)j * DRR + rq);
        Rst[rq + 0][j] = v.x; Rst[rq + 1][j] = v.y;
        Rst[rq + 2][j] = v.z; Rst[rq + 3][j] = v.w;
    }
    __syncthreads();
    const int jl = tid & 31, tg = tid >> 5;
    float acc[8][8];
    #pragma unroll
    for (int a = 0; a < 8; a++)
        #pragma unroll
        for (int b = 0; b < 8; b++) acc[a][b] = 0.f;
    #pragma unroll
    for (int r = 0; r < 32; r++) {
        float qv[8], rv[8];
        #pragma unroll
        for (int tk = 0; tk < 8; tk++) qv[tk] = qrs[tg + 8 * tk][r];
        #pragma unroll
        for (int jc = 0; jc < 8; jc++) rv[jc] = Rst[r][jl + 32 * jc];
        #pragma unroll
        for (int tk = 0; tk < 8; tk++)
            #pragma unroll
            for (int jc = 0; jc < 8; jc++) acc[tk][jc] += qv[tk] * rv[jc];
    }
    #pragma unroll
    for (int tk = 0; tk < 8; tk++) {
        int t = tg + 8 * tk;
        float qb = g_qb[bi * TT + t];
        size_t base = ((size_t)bi * TT + t) * NN;
        #pragma unroll
        for (int jc = 0; jc < 8; jc++)
            g_S[base + jl + 32 * jc] = acc[tk][jc] + qb;
    }
}

// --------------------------------------------- P3: S += q.k^T  (per (b,t), NT)
__global__ __launch_bounds__(256, 2) void k_p3() {
    __shared__ float As[16][132];
    __shared__ float Bs[16][132];
    const int tid = threadIdx.x;
    const int bt = blockIdx.y;
    const int i0 = (blockIdx.x & 1) * 128;
    const int j0 = (blockIdx.x >> 1) * 128;
    const float* Aa = g_qT + (size_t)bt * (NN * 128) + (size_t)i0 * 128;
    const float* Bb = g_kT + (size_t)bt * (NN * 128) + (size_t)j0 * 128;
    const int tx = tid & 15, ty = tid >> 4;
    ull acc2[8][4];
    #pragma unroll
    for (int i = 0; i < 8; i++)
        #pragma unroll
        for (int p = 0; p < 4; p++) acc2[i][p] = 0ull;
    const int lr = tid >> 2;
    const int lk = (tid & 3) * 4;
    for (int k0 = 0; k0 < 128; k0 += 16) {
        #pragma unroll
        for (int it = 0; it < 2; it++) {
            int row = lr + it * 64;
            float4 av = *(const float4*)(Aa + (size_t)row * 128 + k0 + lk);
            As[lk + 0][row] = av.x; As[lk + 1][row] = av.y;
            As[lk + 2][row] = av.z; As[lk + 3][row] = av.w;
            float4 bv = *(const float4*)(Bb + (size_t)row * 128 + k0 + lk);
            Bs[lk + 0][row] = bv.x; Bs[lk + 1][row] = bv.y;
            Bs[lk + 2][row] = bv.z; Bs[lk + 3][row] = bv.w;
        }
        __syncthreads();
        #pragma unroll
        for (int kk = 0; kk < 16; kk++) {
            float4 a0 = *(const float4*)&As[kk][ty * 8];
            float4 a1 = *(const float4*)&As[kk][ty * 8 + 4];
            float4 b0 = *(const float4*)&Bs[kk][tx * 4];
            float4 b1 = *(const float4*)&Bs[kk][64 + tx * 4];
            ull b2[4];
            b2[0] = ((ull*)&b0)[0]; b2[1] = ((ull*)&b0)[1];
            b2[2] = ((ull*)&b1)[0]; b2[3] = ((ull*)&b1)[1];
            float av8[8] = {a0.x, a0.y, a0.z, a0.w, a1.x, a1.y, a1.z, a1.w};
            #pragma unroll
            for (int i = 0; i < 8; i++) {
                ull a2 = dup2(av8[i]);
                fma2(acc2[i][0], a2, b2[0]);
                fma2(acc2[i][1], a2, b2[1]);
                fma2(acc2[i][2], a2, b2[2]);
                fma2(acc2[i][3], a2, b2[3]);
            }
        }
        __syncthreads();
    }
    const int b = bt >> 6, t = bt & 63;
    #pragma unroll
    for (int i = 0; i < 8; i++) {
        int irow = i0 + ty * 8 + i;
        size_t base = ((size_t)((b * NN + irow) * TT + t)) * NN + j0;
        float v[8];
        #pragma unroll
        for (int p = 0; p < 4; p++) {
            float2 f = unpk(acc2[i][p]);
            v[p * 2] = f.x; v[p * 2 + 1] = f.y;
        }
        #pragma unroll
        for (int g = 0; g < 2; g++) {
            int cc = g * 64 + tx * 4;
            float4 o = *(float4*)(g_S + base + cc);
            o.x += v[g*4+0]; o.y += v[g*4+1];
            o.z += v[g*4+2]; o.w += v[g*4+3];
            *(float4*)(g_S + base + cc) = o;
        }
    }
}

// --------------------------------------------- P4a: softmax over t, mask, wsum
__global__ __launch_bounds__(256) void k_p4a() {
    const int bi = blockIdx.x;
    const int i = bi & 255;
    const int j = threadIdx.x;
    size_t base = (size_t)bi * (TT * NN) + j;
    float v[64];
    float mx = -1e30f;
    #pragma unroll
    for (int t = 0; t < 64; t++) { v[t] = g_S[base + t * NN]; mx = fmaxf(mx, v[t]); }
    float s = 0.f;
    #pragma unroll
    for (int t = 0; t < 64; t++) { v[t] = __expf(v[t] - mx); s += v[t]; }
    float inv = (j == i) ? 0.f : (1.f / s);
    #pragma unroll
    for (int t = 0; t < 64; t++) { v[t] *= inv; g_S[base + t * NN] = v[t]; }
    __shared__ float ws[8][64];
    const int lane = j & 31, wp = j >> 5;
    #pragma unroll
    for (int t = 0; t < 64; t++) {
        float r = v[t];
        r += __shfl_xor_sync(0xffffffffu, r, 16);
        r += __shfl_xor_sync(0xffffffffu, r, 8);
        r += __shfl_xor_sync(0xffffffffu, r, 4);
        r += __shfl_xor_sync(0xffffffffu, r, 2);
        r += __shfl_xor_sync(0xffffffffu, r, 1);
        if (lane == 0) ws[wp][t] = r;
    }
    __syncthreads();
    if (j < 64) {
        float s2 = 0.f;
        #pragma unroll
        for (int w = 0; w < 8; w++) s2 += ws[w][j];
        g_wsum[bi * TT + j] = s2;
    }
}

// ------------------------------- P4b: WR = w.R ; P = A'*wsum + WR@W3^T
__global__ __launch_bounds__(256) void k_p4b(const float* __restrict__ R,
                                             const float* __restrict__ Wf) {
    __shared__ float wj[64][72];
    __shared__ float Rs[64][36];
    __shared__ float WRs[64][32];
    __shared__ float wsum_s[64];
    const int bi = blockIdx.x;
    const int tid = threadIdx.x;
    const int rq = tid & 7, tq = tid >> 3;     // tq 0..31; t in {tq, tq+32}
    float a00 = 0.f, a01 = 0.f, a02 = 0.f, a03 = 0.f;
    float a10 = 0.f, a11 = 0.f, a12 = 0.f, a13 = 0.f;
    for (int jc = 0; jc < 4; jc++) {
        const int j0 = jc * 64;
        #pragma unroll
        for (int it = 0; it < 4; it++) {
            int id = tid + it * 256;
            int t = id >> 4, j4 = (id & 15) * 4;
            float4 v = *(const float4*)(g_S + (size_t)bi * (TT * NN) + (size_t)t * NN + j0 + j4);
            *(float4*)&wj[t][j4] = v;
        }
        #pragma unroll
        for (int it = 0; it < 2; it++) {
            int id = tid + it * 256;
            int jj = id >> 3, rr4 = (id & 7) * 4;
            float4 v = *(const float4*)(R + ((size_t)bi * NN + j0 + jj) * DRR + rr4);
            *(float4*)&Rs[jj][rr4] = v;
        }
        __syncthreads();
        #pragma unroll 8
        for (int jj = 0; jj < 64; jj++) {
            float4 rv = *(float4*)&Rs[jj][rq * 4];
            float w0 = wj[tq][jj];
            float w1 = wj[tq + 32][jj];
            a00 += w0 * rv.x; a01 += w0 * rv.y; a02 += w0 * rv.z; a03 += w0 * rv.w;
            a10 += w1 * rv.x; a11 += w1 * rv.y; a12 += w1 * rv.z; a13 += w1 * rv.w;
        }
        __syncthreads();
    }
    *(float4*)&WRs[tq][rq * 4]      = make_float4(a00, a01, a02, a03);
    *(float4*)&WRs[tq + 32][rq * 4] = make_float4(a10, a11, a12, a13);
    if (tid < 64) wsum_s[tid] = g_wsum[bi * TT + tid];
    __syncthreads();
    // phase 2: P[t][e] = Ap[t][e]*wsum[t] + sum_r WRs[t][r]*W3[e][r]
    const int e = tid & 127, th = tid >> 7;
    float w3r[32];
    #pragma unroll
    for (int q = 0; q < 8; q++) {
        float4 v = *(const float4*)(Wf + (size_t)e * 416 + 256 + q * 4);
        w3r[q*4+0] = v.x; w3r[q*4+1] = v.y; w3r[q*4+2] = v.z; w3r[q*4+3] = v.w;
    }
    #pragma unroll 4
    for (int tt = 0; tt < 32; tt++) {
        int t = th * 32 + tt;
        size_t idx = ((size_t)bi * TT + t) * 128 + e;
        float acc = g_Ap[idx] * wsum_s[t];
        #pragma unroll
        for (int q = 0; q < 8; q++) {
            float4 wr = *(float4*)&WRs[t][q * 4];
            acc += wr.x * w3r[q*4+0] + wr.y * w3r[q*4+1]
                 + wr.z * w3r[q*4+2] + wr.w * w3r[q*4+3];
        }
        g_P[idx] = acc;
    }
}

// --------------------------------------------- P5: P += w @ Btil (per (b,t))
__global__ __launch_bounds__(256, 2) void k_p5() {
    __shared__ float As[16][132];
    __shared__ float Bs[16][128];
    const int tid = threadIdx.x;
    const int bt = blockIdx.y;
    const int i0 = blockIdx.x * 128;
    const int b = bt >> 6, t = bt & 63;
    const int tx = tid & 15, ty = tid >> 4;
    ull acc2[8][4];
    #pragma unroll
    for (int i = 0; i < 8; i++)
        #pragma unroll
        for (int p = 0; p < 4; p++) acc2[i][p] = 0ull;
    const int lr = tid >> 2;
    const int lk = (tid & 3) * 4;
    for (int k0 = 0; k0 < 256; k0 += 16) {
        #pragma unroll
        for (int it = 0; it < 2; it++) {
            int row = lr + it * 64;
            size_t abase = ((size_t)((b * NN + i0 + row) * TT + t)) * NN;
            float4 av = *(const float4*)(g_S + abase + k0 + lk);
            As[lk + 0][row] = av.x; As[lk + 1][row] = av.y;
            As[lk + 2][row] = av.z; As[lk + 3][row] = av.w;
        }
        #pragma unroll
        for (int it = 0; it < 2; it++) {
            int id = tid + it * 256;
            int kk = id >> 5, e4 = (id & 31) * 4;
            float4 bv = *(const float4*)(g_Bt + (size_t)bt * (NN * 128) + (size_t)(k0 + kk) * 128 + e4);
            *(float4*)&Bs[kk][e4] = bv;
        }
        __syncthreads();
        #pragma unroll
        for (int kk = 0; kk < 16; kk++) {
            float4 a0 = *(const float4*)&As[kk][ty * 8];
            float4 a1 = *(const float4*)&As[kk][ty * 8 + 4];
            float4 b0 = *(const float4*)&Bs[kk][tx * 4];
            float4 b1 = *(const float4*)&Bs[kk][64 + tx * 4];
            ull b2[4];
            b2[0] = ((ull*)&b0)[0]; b2[1] = ((ull*)&b0)[1];
            b2[2] = ((ull*)&b1)[0]; b2[3] = ((ull*)&b1)[1];
            float av8[8] = {a0.x, a0.y, a0.z, a0.w, a1.x, a1.y, a1.z, a1.w};
            #pragma unroll
            for (int i = 0; i < 8; i++) {
                ull a2 = dup2(av8[i]);
                fma2(acc2[i][0], a2, b2[0]);
                fma2(acc2[i][1], a2, b2[1]);
                fma2(acc2[i][2], a2, b2[2]);
                fma2(acc2[i][3], a2, b2[3]);
            }
        }
        __syncthreads();
    }
    #pragma unroll
    for (int i = 0; i < 8; i++) {
        int irow = i0 + ty * 8 + i;
        size_t base = ((size_t)((b * NN + irow) * TT + t)) * 128;
        float v[8];
        #pragma unroll
        for (int p = 0; p < 4; p++) {
            float2 f = unpk(acc2[i][p]);
            v[p * 2] = f.x; v[p * 2 + 1] = f.y;
        }
        #pragma unroll
        for (int g = 0; g < 2; g++) {
            int cc = g * 64 + tx * 4;
            float4 o = *(float4*)(g_P + base + cc);
            o.x += v[g*4+0]; o.y += v[g*4+1];
            o.z += v[g*4+2]; o.w += v[g*4+3];
            *(float4*)(g_P + base + cc) = o;
        }
    }
}

// --------------------------------------------- P6: layernorm
__global__ __launch_bounds__(128) void k_p6(const float* __restrict__ Hm,
                                            const float* __restrict__ gamma,
                                            const float* __restrict__ beta,
                                            float* __restrict__ out) {
    const int row = blockIdx.x;
    const int d = threadIdx.x;
    size_t idx = (size_t)row * 128 + d;
    float x = Hm[idx] + g_P[idx];
    __shared__ float sm[4], sm2[4];
    float v = x;
    #pragma unroll
    for (int o = 16; o > 0; o >>= 1) v += __shfl_xor_sync(0xffffffffu, v, o);
    if ((d & 31) == 0) sm[d >> 5] = v;
    __syncthreads();
    float mu = (sm[0] + sm[1] + sm[2] + sm[3]) * (1.f / 128.f);
    float dx = x - mu;
    v = dx * dx;
    #pragma unroll
    for (int o = 16; o > 0; o >>= 1) v += __shfl_xor_sync(0xffffffffu, v, o);
    if ((d & 31) == 0) sm2[d >> 5] = v;
    __syncthreads();
    float var = (sm2[0] + sm2[1] + sm2[2] + sm2[3]) * (1.f / 128.f);
    out[idx] = dx * rsqrtf(var + 1e-5f) * gamma[d] + beta[d];
}

// ---------------------------------------------------------------------------
extern "C" void kernel_launch(void* const* d_in, const int* in_sizes, int n_in,
                              void* d_out, int out_size) {
    const float* H     = (const float*)d_in[0];
    const float* R     = (const float*)d_in[1];
    const float* dH    = (const float*)d_in[2];
    const float* Wq    = (const float*)d_in[3];
    const float* bq    = (const float*)d_in[4];
    const float* Wk    = (const float*)d_in[5];
    const float* bk    = (const float*)d_in[6];
    const float* Wr    = (const float*)d_in[7];
    const float* br    = (const float*)d_in[8];
    const float* Wf    = (const float*)d_in[9];
    const float* bf    = (const float*)d_in[10];
    const float* gamma = (const float*)d_in[11];
    const float* beta  = (const float*)d_in[12];
    float* out = (float*)d_out;

    k_prep<<<545, 128>>>(Wq, bq, Wk, bk, Wr, br, Wf, bf);
    k_ej<<<BB * NN, 128>>>(dH, Wf);
    k_p1<<<dim3(512, 4), 256>>>(H);
    k_qr<<<512, 256>>>(H);
    k_p2<<<BB * NN, 256>>>(R);
    k_p3<<<dim3(4, BB * TT), 256>>>();
    k_p4a<<<BB * NN, 256>>>();
    k_p4b<<<BB * NN, 256>>>(R, Wf);
    k_p5<<<dim3(2, BB * TT), 256>>>();
    k_p6<<<BB * NN * TT, 128>>>(H, gamma, beta, out);
}